// round 1
// baseline (speedup 1.0000x reference)
#include <cuda_runtime.h>
#include <cuda_bf16.h>
#include <math.h>

#define NB 4
#define C 128
#define CC 64
#define H0 256
#define HD 64
#define EPS6 1e-6f
#define BN_INV 0.9999950000374997f  // 1/sqrt(1+1e-5)

// ---------------- scratch (device globals; no allocation) ----------------
__device__ float g_xdown[NB*C*HD*HD];        // [n][128][64][64]
__device__ float g_thin [NB*CC*HD*HD];       // theta conv out [n][64][4096]
__device__ float g_g0   [NB*CC*1024];        // g conv+pool [n][64][1024]
__device__ float g_phi0 [NB*CC*1024];        // phi conv+pool [n][64][1024]
__device__ float g_pool [3][NB*CC*85];       // pyramid avg pools per branch
__device__ float g_ppc  [3][NB*85*16];       // level conv+bn+relu [n][s][16]
__device__ float g_thetaf[NB*4096*CC];       // [n][q][64]
__device__ float g_gv   [NB*1024*CC];        // [n][v][64]
__device__ float g_phim [NB*CC*1024];        // [n][64][1024]
__device__ float g_d1   [NB*4096];
__device__ float g_d2   [NB*1024];
__device__ float g_yatt [NB*4096*CC];        // [n][q][64]
__device__ float g_z    [NB*C*4096];         // [n][128][64][64]

// ---------------- K1: depthwise stride-4 4x4 conv ----------------
__global__ void k_down(const float* __restrict__ x, const float* __restrict__ dw){
    int idx = blockIdx.x*blockDim.x + threadIdx.x;
    if (idx >= NB*C*HD*HD) return;
    int j = idx & 63, i = (idx>>6) & 63, nc = idx>>12;
    int ch = nc & (C-1);
    const float* xb = x + ((size_t)nc<<16) + i*4*256 + j*4;
    const float* w = dw + ch*16;
    float s = 0.f;
    #pragma unroll
    for (int a=0; a<4; a++){
        float4 v = *(const float4*)(xb + a*256);
        s += v.x*w[a*4+0] + v.y*w[a*4+1] + v.z*w[a*4+2] + v.w*w[a*4+3];
    }
    g_xdown[idx] = s;
}

// ---------------- K2: theta 1x1 conv 128->64 over 64x64 ----------------
__global__ void k_conv_theta(const float* __restrict__ w, const float* __restrict__ b){
    __shared__ float xs[128][65];
    int bid = blockIdx.x;                  // NB*64 blocks
    int n = bid >> 6; int t0 = (bid & 63) << 6;
    const float* xin = g_xdown + (size_t)n*C*4096;
    for (int idx = threadIdx.x; idx < 128*64; idx += 256){
        int cc_ = idx>>6, p = idx&63;
        xs[cc_][p] = xin[cc_*4096 + t0 + p];
    }
    __syncthreads();
    int o = threadIdx.x >> 2, grp = threadIdx.x & 3;
    const float* wo = w + o*128;
    float acc[16];
    float bo = b[o];
    #pragma unroll
    for (int i=0;i<16;i++) acc[i] = bo;
    for (int c=0;c<128;c++){
        float wv = __ldg(&wo[c]);
        #pragma unroll
        for (int i=0;i<16;i++) acc[i] += wv * xs[c][grp*16+i];
    }
    float* op = g_thin + ((size_t)n*CC + o)*4096 + t0 + grp*16;
    #pragma unroll
    for (int i=0;i<16;i++) op[i] = acc[i];
}

// ---------------- K3: fused g/phi 1x1 conv + 2x2 maxpool ----------------
__global__ void k_conv_pool_gphi(const float* __restrict__ gw, const float* __restrict__ gb,
                                 const float* __restrict__ pw, const float* __restrict__ pb){
    __shared__ float xs[128][65];
    int bid = blockIdx.x;                  // NB*64 blocks (8x8 tiles of 8x8 px)
    int n = bid >> 6; int tb = bid & 63; int by = tb>>3, bx = tb&7;
    const float* xin = g_xdown + (size_t)n*C*4096;
    int base = by*8*64 + bx*8;
    for (int idx = threadIdx.x; idx < 128*64; idx += 256){
        int c_ = idx>>6, p = idx&63;
        xs[c_][p] = xin[c_*4096 + base + (p>>3)*64 + (p&7)];
    }
    __syncthreads();
    int o = threadIdx.x >> 2, py = threadIdx.x & 3;
    float ga[16], pa[16];
    float gbi = gb[o], pbi = pb[o];
    #pragma unroll
    for (int i=0;i<16;i++){ ga[i]=gbi; pa[i]=pbi; }
    const float* gwo = gw + o*128;
    const float* pwo = pw + o*128;
    for (int c=0;c<128;c++){
        float wg = __ldg(&gwo[c]), wp = __ldg(&pwo[c]);
        #pragma unroll
        for (int i=0;i<16;i++){ float xv = xs[c][py*16+i]; ga[i]+=wg*xv; pa[i]+=wp*xv; }
    }
    int vy = by*4 + py;
    float* gout = g_g0  + ((size_t)n*CC+o)*1024 + vy*32 + bx*4;
    float* pout = g_phi0+ ((size_t)n*CC+o)*1024 + vy*32 + bx*4;
    #pragma unroll
    for (int px=0;px<4;px++){
        float m1 = fmaxf(fmaxf(ga[2*px],ga[2*px+1]), fmaxf(ga[8+2*px],ga[8+2*px+1]));
        float m2 = fmaxf(fmaxf(pa[2*px],pa[2*px+1]), fmaxf(pa[8+2*px],pa[8+2*px+1]));
        gout[px]=m1; pout[px]=m2;
    }
}

// ---------------- K4: pyramid average pools (8,4,2,1) ----------------
// br: 0=g(H=32), 1=theta(H=64), 2=phi(H=32)
__global__ void k_pool(int br, int H){
    __shared__ float s8[64], s4[16], s2[4];
    int nc = blockIdx.x;                   // NB*64 blocks, 64 threads
    const float* in = (br==0) ? g_g0 : (br==1) ? g_thin : g_phi0;
    const float* p = in + (size_t)nc*H*H;
    int t = threadIdx.x;
    int k0 = H >> 3;
    int cy = t>>3, cx = t&7;
    float s = 0.f;
    for (int a=0;a<k0;a++)
        for (int b2=0;b2<k0;b2++)
            s += p[(cy*k0+a)*H + cx*k0 + b2];
    s8[t] = s;
    __syncthreads();
    float* ob = g_pool[br] + nc*85;
    ob[t] = s8[t] / (float)(k0*k0);
    if (t < 16){
        int yy=t>>2, xx=t&3;
        float v = s8[(2*yy)*8+2*xx] + s8[(2*yy)*8+2*xx+1] + s8[(2*yy+1)*8+2*xx] + s8[(2*yy+1)*8+2*xx+1];
        s4[t]=v; ob[64+t] = v / (float)(4*k0*k0);
    }
    __syncthreads();
    if (t < 4){
        int yy=t>>1, xx=t&1;
        float v = s4[(2*yy)*4+2*xx] + s4[(2*yy)*4+2*xx+1] + s4[(2*yy+1)*4+2*xx] + s4[(2*yy+1)*4+2*xx+1];
        s2[t]=v; ob[80+t] = v / (float)(16*k0*k0);
    }
    __syncthreads();
    if (t == 0) ob[84] = (s2[0]+s2[1]+s2[2]+s2[3]) / (float)(64*k0*k0);
}

// ---------------- K5: per-level 1x1 conv + BN + relu ----------------
__global__ void k_levelconv(int br, const float* __restrict__ pw,
                            const float* __restrict__ gamma, const float* __restrict__ beta){
    int idx = blockIdx.x*blockDim.x + threadIdx.x;
    if (idx >= NB*85*16) return;
    int o = idx & 15, s = (idx>>4) % 85, n = idx / (85*16);
    int lvl = (s<64) ? 0 : (s<80 ? 1 : (s<84 ? 2 : 3));
    const float* w = pw + (lvl*16+o)*64;
    const float* pl = g_pool[br] + n*64*85 + s;
    float acc = 0.f;
    for (int c=0;c<64;c++) acc += w[c]*pl[c*85];
    acc = acc*BN_INV*gamma[lvl*16+o] + beta[lvl*16+o];
    g_ppc[br][(n*85+s)*16+o] = fmaxf(acc, 0.f);
}

// ---------------- K6: pyramid final conv (concat 128 -> 64) ----------------
__global__ void k_ppfinal(int br, const float* __restrict__ ow, const float* __restrict__ ob, int H){
    __shared__ float xs[64][65];
    __shared__ float us[64][65];
    int P = H*H;
    int bpn = P >> 6;
    int bid = blockIdx.x;
    int n = bid / bpn; int t0 = (bid % bpn) << 6;
    const float* X = (br==0) ? g_g0 : (br==1) ? g_thin : g_phi0;
    const float* xin = X + (size_t)n*CC*P;
    for (int idx = threadIdx.x; idx < 64*64; idx += 256){
        int c_ = idx>>6, p = idx&63;
        xs[c_][p] = xin[c_*P + t0 + p];
    }
    const float* pn = g_ppc[br] + n*85*16;
    float invH = 1.0f / (float)H;
    for (int e = threadIdx.x; e < 4096; e += 256){
        int p = e>>6, u = e&63;
        int lvl = u>>4, j = u&15;
        int pix = t0 + p; int y = pix / H, x = pix % H;
        int ps = 8 >> lvl;
        int off = (lvl==0) ? 0 : (lvl==1 ? 64 : (lvl==2 ? 80 : 84));
        float sy = fminf(fmaxf((y+0.5f)*ps*invH - 0.5f, 0.f), (float)(ps-1));
        float sx = fminf(fmaxf((x+0.5f)*ps*invH - 0.5f, 0.f), (float)(ps-1));
        int yl=(int)sy; int yh=min(yl+1, ps-1); float fy=sy-yl;
        int xl=(int)sx; int xh=min(xl+1, ps-1); float fx=sx-xl;
        const float* b00 = pn + (off + yl*ps + xl)*16;
        const float* b01 = pn + (off + yl*ps + xh)*16;
        const float* b10 = pn + (off + yh*ps + xl)*16;
        const float* b11 = pn + (off + yh*ps + xh)*16;
        us[p][u] = (b00[j]*(1.f-fx)+b01[j]*fx)*(1.f-fy) + (b10[j]*(1.f-fx)+b11[j]*fx)*fy;
    }
    __syncthreads();
    int o = threadIdx.x >> 2, grp = threadIdx.x & 3;
    const float* wo = ow + o*128;
    float acc[16];
    float bo = ob[o];
    #pragma unroll
    for (int i=0;i<16;i++) acc[i]=bo;
    for (int c=0;c<64;c++){
        float wv = __ldg(&wo[c]);
        #pragma unroll
        for (int i=0;i<16;i++) acc[i] += wv*xs[c][grp*16+i];
    }
    for (int u=0;u<64;u++){
        float wv = __ldg(&wo[64+u]);
        #pragma unroll
        for (int i=0;i<16;i++) acc[i] += wv*us[grp*16+i][u];
    }
    #pragma unroll
    for (int i=0;i<16;i++){
        int pix = t0 + grp*16 + i;
        float v = acc[i];
        if (br == 1)      g_thetaf[((size_t)n*4096 + pix)*64 + o] = v;   // [n][q][64]
        else if (br == 0) g_gv   [((size_t)n*1024 + pix)*64 + o] = v;    // [n][v][64]
        else              g_phim [((size_t)n*64 + o)*1024 + pix] = v;    // [n][64][v]
    }
}

// ---------------- K7: depth resize (align_corners=True) ----------------
__device__ __forceinline__ float bil256(const float* p, float sy, float sx){
    int yl=(int)sy; int yh=min(yl+1,255); float fy=sy-yl;
    int xl=(int)sx; int xh=min(xl+1,255); float fx=sx-xl;
    return (p[yl*256+xl]*(1.f-fx)+p[yl*256+xh]*fx)*(1.f-fy)
         + (p[yh*256+xl]*(1.f-fx)+p[yh*256+xh]*fx)*fy;
}
__global__ void k_depth(const float* __restrict__ dm){
    int idx = blockIdx.x*blockDim.x + threadIdx.x;
    const int T1 = NB*4096;
    if (idx < T1){
        int n = idx>>12; int q = idx & 4095; int yy = q>>6, xx = q&63;
        float sy = (float)(yy*255)/63.f, sx = (float)(xx*255)/63.f;
        g_d1[idx] = bil256(dm + (size_t)n*65536, sy, sx);
    } else if (idx < T1 + NB*1024){
        int r = idx - T1; int n = r>>10; int q = r & 1023; int yy = q>>5, xx = q&31;
        float sy = (float)(yy*255)/31.f, sx = (float)(xx*255)/31.f;
        g_d2[r] = bil256(dm + (size_t)n*65536, sy, sx);
    }
}

// ---------------- K8: fused attention ----------------
// block: 512 thr = 16 warps = 16 q rows; grid = NB*4096/16 = 1024
__global__ void __launch_bounds__(512) k_attn(){
    __shared__ float th[16*64];
    __shared__ float ch[8*1024];   // phi chunks, then g chunks [128][64]
    int n = blockIdx.x >> 8;
    int q0 = (blockIdx.x & 255) * 16;
    const float* tf = g_thetaf + ((size_t)n*4096 + q0)*64;
    for (int i = threadIdx.x; i < 16*64; i += 512) th[i] = tf[i];
    int w = threadIdx.x >> 5, lane = threadIdx.x & 31;

    float acc[32];
    #pragma unroll
    for (int m=0;m<32;m++) acc[m]=0.f;
    const float* ph = g_phim + (size_t)n*64*1024;
    for (int c0=0;c0<64;c0+=8){
        __syncthreads();
        for (int i = threadIdx.x; i < 8*1024; i += 512) ch[i] = ph[c0*1024 + i];
        __syncthreads();
        #pragma unroll
        for (int k=0;k<8;k++){
            float tv = th[w*64 + c0 + k];
            #pragma unroll
            for (int m=0;m<32;m++) acc[m] += tv * ch[k*1024 + m*32 + lane];
        }
    }
    // softmax(Ra)
    float mx = -1e30f;
    #pragma unroll
    for (int m=0;m<32;m++) mx = fmaxf(mx, acc[m]);
    for (int o=16;o;o>>=1) mx = fmaxf(mx, __shfl_xor_sync(0xffffffffu, mx, o));
    float sm = 0.f;
    #pragma unroll
    for (int m=0;m<32;m++){ acc[m] = expf(acc[m]-mx); sm += acc[m]; }
    for (int o=16;o;o>>=1) sm += __shfl_xor_sync(0xffffffffu, sm, o);
    float inv1 = 1.f/sm;
    // Rd
    float d1q = g_d1[n*4096 + q0 + w];
    float rd[32];
    float mx2 = -1e30f;
    #pragma unroll
    for (int m=0;m<32;m++){
        float dv = g_d2[n*1024 + m*32 + lane];
        float r = fminf(d1q/(dv+EPS6), dv/(d1q+EPS6));
        rd[m] = r; mx2 = fmaxf(mx2, r);
    }
    for (int o=16;o;o>>=1) mx2 = fmaxf(mx2, __shfl_xor_sync(0xffffffffu, mx2, o));
    float sm2 = 0.f;
    #pragma unroll
    for (int m=0;m<32;m++){ rd[m] = expf(rd[m]-mx2); sm2 += rd[m]; }
    for (int o=16;o;o>>=1) sm2 += __shfl_xor_sync(0xffffffffu, sm2, o);
    float inv2 = 1.f/sm2;
    // S = softmax(Ra*Rd)
    float mx3 = -1e30f;
    #pragma unroll
    for (int m=0;m<32;m++){ acc[m] = (acc[m]*inv1)*(rd[m]*inv2); mx3 = fmaxf(mx3, acc[m]); }
    for (int o=16;o;o>>=1) mx3 = fmaxf(mx3, __shfl_xor_sync(0xffffffffu, mx3, o));
    float sm3 = 0.f;
    #pragma unroll
    for (int m=0;m<32;m++){ acc[m] = expf(acc[m]-mx3); sm3 += acc[m]; }
    for (int o=16;o;o>>=1) sm3 += __shfl_xor_sync(0xffffffffu, sm3, o);
    float inv3 = 1.f/sm3;
    #pragma unroll
    for (int m=0;m<32;m++) acc[m] *= inv3;
    // y = S @ g  (lane owns c=2*lane, 2*lane+1)
    float y0 = 0.f, y1 = 0.f;
    const float* gb = g_gv + (size_t)n*1024*64;
    for (int vb=0; vb<8; vb++){
        __syncthreads();
        for (int i = threadIdx.x; i < 128*64; i += 512) ch[i] = gb[vb*128*64 + i];
        __syncthreads();
        #pragma unroll
        for (int mm=0;mm<4;mm++){
            int m = vb*4 + mm;
            #pragma unroll
            for (int j=0;j<32;j++){
                float s = __shfl_sync(0xffffffffu, acc[m], j);
                float2 gvv = *(const float2*)&ch[(mm*32+j)*64 + 2*lane];
                y0 += s*gvv.x; y1 += s*gvv.y;
            }
        }
    }
    float* yp = g_yatt + ((size_t)n*4096 + q0 + w)*64;
    yp[2*lane] = y0; yp[2*lane+1] = y1;
}

// ---------------- K9: z = conv1x1(y, z_w, z_b) ----------------
__global__ void k_zconv(const float* __restrict__ zw, const float* __restrict__ zb){
    __shared__ float ys[64][65];
    int bid = blockIdx.x;                  // NB*64
    int n = bid >> 6; int t0 = (bid & 63) << 6;
    const float* yb = g_yatt + ((size_t)n*4096 + t0)*64;
    for (int idx = threadIdx.x; idx < 4096; idx += 256)
        ys[idx>>6][idx&63] = yb[idx];
    __syncthreads();
    int o = threadIdx.x >> 1, grp = threadIdx.x & 1;
    const float* wo = zw + o*64;
    float bo = zb[o];
    float* zp = g_z + ((size_t)n*C + o)*4096 + t0 + grp*32;
    for (int p=0;p<32;p++){
        float acc = bo;
        const float* yr = &ys[grp*32+p][0];
        #pragma unroll
        for (int c=0;c<64;c++) acc += __ldg(&wo[c])*yr[c];
        zp[p] = acc;
    }
}

// ---------------- K10: epilogue: out = x + upsample(z, align=True) ----------------
__global__ void k_epi(const float* __restrict__ x, float* __restrict__ out){
    int idx = blockIdx.x*blockDim.x + threadIdx.x;
    if (idx >= NB*C*H0*H0) return;
    int X_ = idx & 255, Y = (idx>>8) & 255, nch = idx >> 16;
    float sy = (float)(Y*63)/255.f, sx = (float)(X_*63)/255.f;
    int yl=(int)sy, xl=(int)sx;
    int yh=min(yl+1,63), xh=min(xl+1,63);
    float fy=sy-yl, fx=sx-xl;
    const float* zp = g_z + (size_t)nch*4096;
    float v = (zp[yl*64+xl]*(1.f-fx)+zp[yl*64+xh]*fx)*(1.f-fy)
            + (zp[yh*64+xl]*(1.f-fx)+zp[yh*64+xh]*fx)*fy;
    out[idx] = x[idx] + v;
}

// ---------------- host ----------------
extern "C" void kernel_launch(void* const* d_in, const int* in_sizes, int n_in,
                              void* d_out, int out_size){
    const float* x        = (const float*)d_in[0];
    const float* depth    = (const float*)d_in[1];
    const float* down_w   = (const float*)d_in[2];
    const float* theta_w  = (const float*)d_in[3];
    const float* theta_b  = (const float*)d_in[4];
    const float* phi_w    = (const float*)d_in[5];
    const float* phi_b    = (const float*)d_in[6];
    const float* g_w      = (const float*)d_in[7];
    const float* g_b      = (const float*)d_in[8];
    const float* z_w      = (const float*)d_in[9];
    const float* z_b      = (const float*)d_in[10];
    const float* ppg_pw   = (const float*)d_in[11];
    const float* ppg_gam  = (const float*)d_in[12];
    const float* ppg_bet  = (const float*)d_in[13];
    const float* ppg_ow   = (const float*)d_in[14];
    const float* ppg_ob   = (const float*)d_in[15];
    const float* ppt_pw   = (const float*)d_in[16];
    const float* ppt_gam  = (const float*)d_in[17];
    const float* ppt_bet  = (const float*)d_in[18];
    const float* ppt_ow   = (const float*)d_in[19];
    const float* ppt_ob   = (const float*)d_in[20];
    const float* ppp_pw   = (const float*)d_in[21];
    const float* ppp_gam  = (const float*)d_in[22];
    const float* ppp_bet  = (const float*)d_in[23];
    const float* ppp_ow   = (const float*)d_in[24];
    const float* ppp_ob   = (const float*)d_in[25];
    float* out = (float*)d_out;

    // 1. downsample
    k_down<<<(NB*C*HD*HD + 255)/256, 256>>>(x, down_w);
    // 2. theta conv
    k_conv_theta<<<NB*64, 256>>>(theta_w, theta_b);
    // 3. g/phi conv + maxpool
    k_conv_pool_gphi<<<NB*64, 256>>>(g_w, g_b, phi_w, phi_b);
    // 4. pyramid pools
    k_pool<<<NB*64, 64>>>(0, 32);
    k_pool<<<NB*64, 64>>>(1, 64);
    k_pool<<<NB*64, 64>>>(2, 32);
    // 5. level convs
    int lc_grid = (NB*85*16 + 255)/256;
    k_levelconv<<<lc_grid, 256>>>(0, ppg_pw, ppg_gam, ppg_bet);
    k_levelconv<<<lc_grid, 256>>>(1, ppt_pw, ppt_gam, ppt_bet);
    k_levelconv<<<lc_grid, 256>>>(2, ppp_pw, ppp_gam, ppp_bet);
    // 6. pyramid final convs
    k_ppfinal<<<NB*(1024/64), 256>>>(0, ppg_ow, ppg_ob, 32);
    k_ppfinal<<<NB*(4096/64), 256>>>(1, ppt_ow, ppt_ob, 64);
    k_ppfinal<<<NB*(1024/64), 256>>>(2, ppp_ow, ppp_ob, 32);
    // 7. depth resizes
    k_depth<<<(NB*4096 + NB*1024 + 255)/256, 256>>>(depth);
    // 8. attention
    k_attn<<<NB*4096/16, 512>>>();
    // 9. z conv
    k_zconv<<<NB*64, 256>>>(z_w, z_b);
    // 10. epilogue
    k_epi<<<(NB*C*H0*H0 + 255)/256, 256>>>(x, out);
}

// round 2
// speedup vs baseline: 1.0002x; 1.0002x over previous
#include <cuda_runtime.h>
#include <cuda_bf16.h>
#include <math.h>

#define NB 4
#define C 128
#define CC 64
#define H0 256
#define HD 64
#define EPS6 1e-6f
#define BN_INV 0.9999950000374997f  // 1/sqrt(1+1e-5)

// ---------------- scratch (device globals; no allocation) ----------------
__device__ float g_xdown[NB*C*HD*HD];        // [n][128][64][64]
__device__ float g_thin [NB*CC*HD*HD];       // theta conv out [n][64][4096]
__device__ float g_g0   [NB*CC*1024];        // g conv+pool [n][64][1024]
__device__ float g_phi0 [NB*CC*1024];        // phi conv+pool [n][64][1024]
__device__ float g_pool [3][NB*CC*85];       // pyramid avg pools per branch
__device__ float g_ppc  [3][NB*85*16];       // level conv+bn+relu [n][s][16]
__device__ float g_thetaf[NB*4096*CC];       // [n][q][64]
__device__ float g_gv   [NB*1024*CC];        // [n][v][64]
__device__ float g_phim [NB*CC*1024];        // [n][64][1024]
__device__ float g_d1   [NB*4096];
__device__ float g_d2   [NB*1024];
__device__ float g_yatt [NB*4096*CC];        // [n][q][64]
__device__ float g_z    [NB*C*4096];         // [n][128][64][64]

// ---------------- K1: depthwise stride-4 4x4 conv ----------------
__global__ void k_down(const float* __restrict__ x, const float* __restrict__ dw){
    int idx = blockIdx.x*blockDim.x + threadIdx.x;
    if (idx >= NB*C*HD*HD) return;
    int j = idx & 63, i = (idx>>6) & 63, nc = idx>>12;
    int ch = nc & (C-1);
    const float* xb = x + ((size_t)nc<<16) + i*4*256 + j*4;
    const float* w = dw + ch*16;
    float s = 0.f;
    #pragma unroll
    for (int a=0; a<4; a++){
        float4 v = *(const float4*)(xb + a*256);
        s += v.x*w[a*4+0] + v.y*w[a*4+1] + v.z*w[a*4+2] + v.w*w[a*4+3];
    }
    g_xdown[idx] = s;
}

// ---------------- K2: theta 1x1 conv 128->64 over 64x64 ----------------
__global__ void k_conv_theta(const float* __restrict__ w, const float* __restrict__ b){
    __shared__ float xs[128][65];
    int bid = blockIdx.x;                  // NB*64 blocks
    int n = bid >> 6; int t0 = (bid & 63) << 6;
    const float* xin = g_xdown + (size_t)n*C*4096;
    for (int idx = threadIdx.x; idx < 128*64; idx += 256){
        int cc_ = idx>>6, p = idx&63;
        xs[cc_][p] = xin[cc_*4096 + t0 + p];
    }
    __syncthreads();
    int o = threadIdx.x >> 2, grp = threadIdx.x & 3;
    const float* wo = w + o*128;
    float acc[16];
    float bo = b[o];
    #pragma unroll
    for (int i=0;i<16;i++) acc[i] = bo;
    for (int c=0;c<128;c++){
        float wv = __ldg(&wo[c]);
        #pragma unroll
        for (int i=0;i<16;i++) acc[i] += wv * xs[c][grp*16+i];
    }
    float* op = g_thin + ((size_t)n*CC + o)*4096 + t0 + grp*16;
    #pragma unroll
    for (int i=0;i<16;i++) op[i] = acc[i];
}

// ---------------- K3: fused g/phi 1x1 conv + 2x2 maxpool ----------------
__global__ void k_conv_pool_gphi(const float* __restrict__ gw, const float* __restrict__ gb,
                                 const float* __restrict__ pw, const float* __restrict__ pb){
    __shared__ float xs[128][65];
    int bid = blockIdx.x;                  // NB*64 blocks (8x8 tiles of 8x8 px)
    int n = bid >> 6; int tb = bid & 63; int by = tb>>3, bx = tb&7;
    const float* xin = g_xdown + (size_t)n*C*4096;
    int base = by*8*64 + bx*8;
    for (int idx = threadIdx.x; idx < 128*64; idx += 256){
        int c_ = idx>>6, p = idx&63;
        xs[c_][p] = xin[c_*4096 + base + (p>>3)*64 + (p&7)];
    }
    __syncthreads();
    int o = threadIdx.x >> 2, py = threadIdx.x & 3;
    float ga[16], pa[16];
    float gbi = gb[o], pbi = pb[o];
    #pragma unroll
    for (int i=0;i<16;i++){ ga[i]=gbi; pa[i]=pbi; }
    const float* gwo = gw + o*128;
    const float* pwo = pw + o*128;
    for (int c=0;c<128;c++){
        float wg = __ldg(&gwo[c]), wp = __ldg(&pwo[c]);
        #pragma unroll
        for (int i=0;i<16;i++){ float xv = xs[c][py*16+i]; ga[i]+=wg*xv; pa[i]+=wp*xv; }
    }
    int vy = by*4 + py;
    float* gout = g_g0  + ((size_t)n*CC+o)*1024 + vy*32 + bx*4;
    float* pout = g_phi0+ ((size_t)n*CC+o)*1024 + vy*32 + bx*4;
    #pragma unroll
    for (int px=0;px<4;px++){
        float m1 = fmaxf(fmaxf(ga[2*px],ga[2*px+1]), fmaxf(ga[8+2*px],ga[8+2*px+1]));
        float m2 = fmaxf(fmaxf(pa[2*px],pa[2*px+1]), fmaxf(pa[8+2*px],pa[8+2*px+1]));
        gout[px]=m1; pout[px]=m2;
    }
}

// ---------------- K4: pyramid average pools (8,4,2,1) ----------------
// br: 0=g(H=32), 1=theta(H=64), 2=phi(H=32)
__global__ void k_pool(int br, int H){
    __shared__ float s8[64], s4[16], s2[4];
    int nc = blockIdx.x;                   // NB*64 blocks, 64 threads
    const float* in = (br==0) ? g_g0 : (br==1) ? g_thin : g_phi0;
    const float* p = in + (size_t)nc*H*H;
    int t = threadIdx.x;
    int k0 = H >> 3;
    int cy = t>>3, cx = t&7;
    float s = 0.f;
    for (int a=0;a<k0;a++)
        for (int b2=0;b2<k0;b2++)
            s += p[(cy*k0+a)*H + cx*k0 + b2];
    s8[t] = s;
    __syncthreads();
    float* ob = g_pool[br] + nc*85;
    ob[t] = s8[t] / (float)(k0*k0);
    if (t < 16){
        int yy=t>>2, xx=t&3;
        float v = s8[(2*yy)*8+2*xx] + s8[(2*yy)*8+2*xx+1] + s8[(2*yy+1)*8+2*xx] + s8[(2*yy+1)*8+2*xx+1];
        s4[t]=v; ob[64+t] = v / (float)(4*k0*k0);
    }
    __syncthreads();
    if (t < 4){
        int yy=t>>1, xx=t&1;
        float v = s4[(2*yy)*4+2*xx] + s4[(2*yy)*4+2*xx+1] + s4[(2*yy+1)*4+2*xx] + s4[(2*yy+1)*4+2*xx+1];
        s2[t]=v; ob[80+t] = v / (float)(16*k0*k0);
    }
    __syncthreads();
    if (t == 0) ob[84] = (s2[0]+s2[1]+s2[2]+s2[3]) / (float)(64*k0*k0);
}

// ---------------- K5: per-level 1x1 conv + BN + relu ----------------
__global__ void k_levelconv(int br, const float* __restrict__ pw,
                            const float* __restrict__ gamma, const float* __restrict__ beta){
    int idx = blockIdx.x*blockDim.x + threadIdx.x;
    if (idx >= NB*85*16) return;
    int o = idx & 15, s = (idx>>4) % 85, n = idx / (85*16);
    int lvl = (s<64) ? 0 : (s<80 ? 1 : (s<84 ? 2 : 3));
    const float* w = pw + (lvl*16+o)*64;
    const float* pl = g_pool[br] + n*64*85 + s;
    float acc = 0.f;
    for (int c=0;c<64;c++) acc += w[c]*pl[c*85];
    acc = acc*BN_INV*gamma[lvl*16+o] + beta[lvl*16+o];
    g_ppc[br][(n*85+s)*16+o] = fmaxf(acc, 0.f);
}

// ---------------- K6: pyramid final conv (concat 128 -> 64) ----------------
__global__ void k_ppfinal(int br, const float* __restrict__ ow, const float* __restrict__ ob, int H){
    __shared__ float xs[64][65];
    __shared__ float us[64][65];
    int P = H*H;
    int bpn = P >> 6;
    int bid = blockIdx.x;
    int n = bid / bpn; int t0 = (bid % bpn) << 6;
    const float* X = (br==0) ? g_g0 : (br==1) ? g_thin : g_phi0;
    const float* xin = X + (size_t)n*CC*P;
    for (int idx = threadIdx.x; idx < 64*64; idx += 256){
        int c_ = idx>>6, p = idx&63;
        xs[c_][p] = xin[c_*P + t0 + p];
    }
    const float* pn = g_ppc[br] + n*85*16;
    float invH = 1.0f / (float)H;
    for (int e = threadIdx.x; e < 4096; e += 256){
        int p = e>>6, u = e&63;
        int lvl = u>>4, j = u&15;
        int pix = t0 + p; int y = pix / H, x = pix % H;
        int ps = 8 >> lvl;
        int off = (lvl==0) ? 0 : (lvl==1 ? 64 : (lvl==2 ? 80 : 84));
        float sy = fminf(fmaxf((y+0.5f)*ps*invH - 0.5f, 0.f), (float)(ps-1));
        float sx = fminf(fmaxf((x+0.5f)*ps*invH - 0.5f, 0.f), (float)(ps-1));
        int yl=(int)sy; int yh=min(yl+1, ps-1); float fy=sy-yl;
        int xl=(int)sx; int xh=min(xl+1, ps-1); float fx=sx-xl;
        const float* b00 = pn + (off + yl*ps + xl)*16;
        const float* b01 = pn + (off + yl*ps + xh)*16;
        const float* b10 = pn + (off + yh*ps + xl)*16;
        const float* b11 = pn + (off + yh*ps + xh)*16;
        us[p][u] = (b00[j]*(1.f-fx)+b01[j]*fx)*(1.f-fy) + (b10[j]*(1.f-fx)+b11[j]*fx)*fy;
    }
    __syncthreads();
    int o = threadIdx.x >> 2, grp = threadIdx.x & 3;
    const float* wo = ow + o*128;
    float acc[16];
    float bo = ob[o];
    #pragma unroll
    for (int i=0;i<16;i++) acc[i]=bo;
    for (int c=0;c<64;c++){
        float wv = __ldg(&wo[c]);
        #pragma unroll
        for (int i=0;i<16;i++) acc[i] += wv*xs[c][grp*16+i];
    }
    for (int u=0;u<64;u++){
        float wv = __ldg(&wo[64+u]);
        #pragma unroll
        for (int i=0;i<16;i++) acc[i] += wv*us[grp*16+i][u];
    }
    #pragma unroll
    for (int i=0;i<16;i++){
        int pix = t0 + grp*16 + i;
        float v = acc[i];
        if (br == 1)      g_thetaf[((size_t)n*4096 + pix)*64 + o] = v;   // [n][q][64]
        else if (br == 0) g_gv   [((size_t)n*1024 + pix)*64 + o] = v;    // [n][v][64]
        else              g_phim [((size_t)n*64 + o)*1024 + pix] = v;    // [n][64][v]
    }
}

// ---------------- K7: depth resize (align_corners=True) ----------------
__device__ __forceinline__ float bil256(const float* p, float sy, float sx){
    int yl=(int)sy; int yh=min(yl+1,255); float fy=sy-yl;
    int xl=(int)sx; int xh=min(xl+1,255); float fx=sx-xl;
    return (p[yl*256+xl]*(1.f-fx)+p[yl*256+xh]*fx)*(1.f-fy)
         + (p[yh*256+xl]*(1.f-fx)+p[yh*256+xh]*fx)*fy;
}
__global__ void k_depth(const float* __restrict__ dm){
    int idx = blockIdx.x*blockDim.x + threadIdx.x;
    const int T1 = NB*4096;
    if (idx < T1){
        int n = idx>>12; int q = idx & 4095; int yy = q>>6, xx = q&63;
        float sy = (float)(yy*255)/63.f, sx = (float)(xx*255)/63.f;
        g_d1[idx] = bil256(dm + (size_t)n*65536, sy, sx);
    } else if (idx < T1 + NB*1024){
        int r = idx - T1; int n = r>>10; int q = r & 1023; int yy = q>>5, xx = q&31;
        float sy = (float)(yy*255)/31.f, sx = (float)(xx*255)/31.f;
        g_d2[r] = bil256(dm + (size_t)n*65536, sy, sx);
    }
}

// ---------------- K8: fused attention ----------------
// block: 512 thr = 16 warps = 16 q rows; grid = NB*4096/16 = 1024
__global__ void __launch_bounds__(512) k_attn(){
    __shared__ float th[16*64];
    __shared__ float ch[8*1024];   // phi chunks, then g chunks [128][64]
    int n = blockIdx.x >> 8;
    int q0 = (blockIdx.x & 255) * 16;
    const float* tf = g_thetaf + ((size_t)n*4096 + q0)*64;
    for (int i = threadIdx.x; i < 16*64; i += 512) th[i] = tf[i];
    int w = threadIdx.x >> 5, lane = threadIdx.x & 31;

    float acc[32];
    #pragma unroll
    for (int m=0;m<32;m++) acc[m]=0.f;
    const float* ph = g_phim + (size_t)n*64*1024;
    for (int c0=0;c0<64;c0+=8){
        __syncthreads();
        for (int i = threadIdx.x; i < 8*1024; i += 512) ch[i] = ph[c0*1024 + i];
        __syncthreads();
        #pragma unroll
        for (int k=0;k<8;k++){
            float tv = th[w*64 + c0 + k];
            #pragma unroll
            for (int m=0;m<32;m++) acc[m] += tv * ch[k*1024 + m*32 + lane];
        }
    }
    // softmax(Ra)
    float mx = -1e30f;
    #pragma unroll
    for (int m=0;m<32;m++) mx = fmaxf(mx, acc[m]);
    for (int o=16;o;o>>=1) mx = fmaxf(mx, __shfl_xor_sync(0xffffffffu, mx, o));
    float sm = 0.f;
    #pragma unroll
    for (int m=0;m<32;m++){ acc[m] = expf(acc[m]-mx); sm += acc[m]; }
    for (int o=16;o;o>>=1) sm += __shfl_xor_sync(0xffffffffu, sm, o);
    float inv1 = 1.f/sm;
    // Rd
    float d1q = g_d1[n*4096 + q0 + w];
    float rd[32];
    float mx2 = -1e30f;
    #pragma unroll
    for (int m=0;m<32;m++){
        float dv = g_d2[n*1024 + m*32 + lane];
        float r = fminf(d1q/(dv+EPS6), dv/(d1q+EPS6));
        rd[m] = r; mx2 = fmaxf(mx2, r);
    }
    for (int o=16;o;o>>=1) mx2 = fmaxf(mx2, __shfl_xor_sync(0xffffffffu, mx2, o));
    float sm2 = 0.f;
    #pragma unroll
    for (int m=0;m<32;m++){ rd[m] = expf(rd[m]-mx2); sm2 += rd[m]; }
    for (int o=16;o;o>>=1) sm2 += __shfl_xor_sync(0xffffffffu, sm2, o);
    float inv2 = 1.f/sm2;
    // S = softmax(Ra*Rd)
    float mx3 = -1e30f;
    #pragma unroll
    for (int m=0;m<32;m++){ acc[m] = (acc[m]*inv1)*(rd[m]*inv2); mx3 = fmaxf(mx3, acc[m]); }
    for (int o=16;o;o>>=1) mx3 = fmaxf(mx3, __shfl_xor_sync(0xffffffffu, mx3, o));
    float sm3 = 0.f;
    #pragma unroll
    for (int m=0;m<32;m++){ acc[m] = expf(acc[m]-mx3); sm3 += acc[m]; }
    for (int o=16;o;o>>=1) sm3 += __shfl_xor_sync(0xffffffffu, sm3, o);
    float inv3 = 1.f/sm3;
    #pragma unroll
    for (int m=0;m<32;m++) acc[m] *= inv3;
    // y = S @ g  (lane owns c=2*lane, 2*lane+1)
    float y0 = 0.f, y1 = 0.f;
    const float* gb = g_gv + (size_t)n*1024*64;
    for (int vb=0; vb<8; vb++){
        __syncthreads();
        for (int i = threadIdx.x; i < 128*64; i += 512) ch[i] = gb[vb*128*64 + i];
        __syncthreads();
        #pragma unroll
        for (int mm=0;mm<4;mm++){
            int m = vb*4 + mm;
            #pragma unroll
            for (int j=0;j<32;j++){
                float s = __shfl_sync(0xffffffffu, acc[m], j);
                float2 gvv = *(const float2*)&ch[(mm*32+j)*64 + 2*lane];
                y0 += s*gvv.x; y1 += s*gvv.y;
            }
        }
    }
    float* yp = g_yatt + ((size_t)n*4096 + q0 + w)*64;
    yp[2*lane] = y0; yp[2*lane+1] = y1;
}

// ---------------- K9: z = conv1x1(y, z_w, z_b) ----------------
__global__ void k_zconv(const float* __restrict__ zw, const float* __restrict__ zb){
    __shared__ float ys[64][65];
    int bid = blockIdx.x;                  // NB*64
    int n = bid >> 6; int t0 = (bid & 63) << 6;
    const float* yb = g_yatt + ((size_t)n*4096 + t0)*64;
    for (int idx = threadIdx.x; idx < 4096; idx += 256)
        ys[idx>>6][idx&63] = yb[idx];
    __syncthreads();
    int o = threadIdx.x >> 1, grp = threadIdx.x & 1;
    const float* wo = zw + o*64;
    float bo = zb[o];
    float* zp = g_z + ((size_t)n*C + o)*4096 + t0 + grp*32;
    for (int p=0;p<32;p++){
        float acc = bo;
        const float* yr = &ys[grp*32+p][0];
        #pragma unroll
        for (int c=0;c<64;c++) acc += __ldg(&wo[c])*yr[c];
        zp[p] = acc;
    }
}

// ---------------- K10: epilogue: out = x + upsample(z, align=True) ----------------
__global__ void k_epi(const float* __restrict__ x, float* __restrict__ out){
    int idx = blockIdx.x*blockDim.x + threadIdx.x;
    if (idx >= NB*C*H0*H0) return;
    int X_ = idx & 255, Y = (idx>>8) & 255, nch = idx >> 16;
    float sy = (float)(Y*63)/255.f, sx = (float)(X_*63)/255.f;
    int yl=(int)sy, xl=(int)sx;
    int yh=min(yl+1,63), xh=min(xl+1,63);
    float fy=sy-yl, fx=sx-xl;
    const float* zp = g_z + (size_t)nch*4096;
    float v = (zp[yl*64+xl]*(1.f-fx)+zp[yl*64+xh]*fx)*(1.f-fy)
            + (zp[yh*64+xl]*(1.f-fx)+zp[yh*64+xh]*fx)*fy;
    out[idx] = x[idx] + v;
}

// ---------------- host ----------------
extern "C" void kernel_launch(void* const* d_in, const int* in_sizes, int n_in,
                              void* d_out, int out_size){
    const float* x        = (const float*)d_in[0];
    const float* depth    = (const float*)d_in[1];
    const float* down_w   = (const float*)d_in[2];
    const float* theta_w  = (const float*)d_in[3];
    const float* theta_b  = (const float*)d_in[4];
    const float* phi_w    = (const float*)d_in[5];
    const float* phi_b    = (const float*)d_in[6];
    const float* g_w      = (const float*)d_in[7];
    const float* g_b      = (const float*)d_in[8];
    const float* z_w      = (const float*)d_in[9];
    const float* z_b      = (const float*)d_in[10];
    const float* ppg_pw   = (const float*)d_in[11];
    const float* ppg_gam  = (const float*)d_in[12];
    const float* ppg_bet  = (const float*)d_in[13];
    const float* ppg_ow   = (const float*)d_in[14];
    const float* ppg_ob   = (const float*)d_in[15];
    const float* ppt_pw   = (const float*)d_in[16];
    const float* ppt_gam  = (const float*)d_in[17];
    const float* ppt_bet  = (const float*)d_in[18];
    const float* ppt_ow   = (const float*)d_in[19];
    const float* ppt_ob   = (const float*)d_in[20];
    const float* ppp_pw   = (const float*)d_in[21];
    const float* ppp_gam  = (const float*)d_in[22];
    const float* ppp_bet  = (const float*)d_in[23];
    const float* ppp_ow   = (const float*)d_in[24];
    const float* ppp_ob   = (const float*)d_in[25];
    float* out = (float*)d_out;

    // 1. downsample
    k_down<<<(NB*C*HD*HD + 255)/256, 256>>>(x, down_w);
    // 2. theta conv
    k_conv_theta<<<NB*64, 256>>>(theta_w, theta_b);
    // 3. g/phi conv + maxpool
    k_conv_pool_gphi<<<NB*64, 256>>>(g_w, g_b, phi_w, phi_b);
    // 4. pyramid pools
    k_pool<<<NB*64, 64>>>(0, 32);
    k_pool<<<NB*64, 64>>>(1, 64);
    k_pool<<<NB*64, 64>>>(2, 32);
    // 5. level convs
    int lc_grid = (NB*85*16 + 255)/256;
    k_levelconv<<<lc_grid, 256>>>(0, ppg_pw, ppg_gam, ppg_bet);
    k_levelconv<<<lc_grid, 256>>>(1, ppt_pw, ppt_gam, ppt_bet);
    k_levelconv<<<lc_grid, 256>>>(2, ppp_pw, ppp_gam, ppp_bet);
    // 6. pyramid final convs
    k_ppfinal<<<NB*(1024/64), 256>>>(0, ppg_ow, ppg_ob, 32);
    k_ppfinal<<<NB*(4096/64), 256>>>(1, ppt_ow, ppt_ob, 64);
    k_ppfinal<<<NB*(1024/64), 256>>>(2, ppp_ow, ppp_ob, 32);
    // 7. depth resizes
    k_depth<<<(NB*4096 + NB*1024 + 255)/256, 256>>>(depth);
    // 8. attention
    k_attn<<<NB*4096/16, 512>>>();
    // 9. z conv
    k_zconv<<<NB*64, 256>>>(z_w, z_b);
    // 10. epilogue
    k_epi<<<(NB*C*H0*H0 + 255)/256, 256>>>(x, out);
}

// round 4
// speedup vs baseline: 1.7823x; 1.7820x over previous
#include <cuda_runtime.h>
#include <cuda_bf16.h>
#include <math.h>
#include <cstdint>

#define NB 4
#define C 128
#define CC 64
#define H0 256
#define HD 64
#define EPS6 1e-6f
#define BN_INV 0.9999950000374997f

// ---------- mma/ldmatrix helpers (baseline PTX, sm_80+) ----------
__device__ __forceinline__ uint32_t s2u(const void* p){
    uint32_t a; asm("{ .reg .u64 t; cvta.to.shared.u64 t, %1; cvt.u32.u64 %0, t; }" : "=r"(a) : "l"(p)); return a;
}
__device__ __forceinline__ void ldsm4(uint32_t* r, uint32_t a){
    asm volatile("ldmatrix.sync.aligned.m8n8.x4.shared.b16 {%0,%1,%2,%3}, [%4];"
        : "=r"(r[0]),"=r"(r[1]),"=r"(r[2]),"=r"(r[3]) : "r"(a));
}
__device__ __forceinline__ void ldsm4t(uint32_t* r, uint32_t a){
    asm volatile("ldmatrix.sync.aligned.m8n8.x4.trans.shared.b16 {%0,%1,%2,%3}, [%4];"
        : "=r"(r[0]),"=r"(r[1]),"=r"(r[2]),"=r"(r[3]) : "r"(a));
}
__device__ __forceinline__ void mma16816(float* d, const uint32_t* a, uint32_t b0, uint32_t b1){
    asm volatile("mma.sync.aligned.m16n8k16.row.col.f32.bf16.bf16.f32 "
        "{%0,%1,%2,%3}, {%4,%5,%6,%7}, {%8,%9}, {%0,%1,%2,%3};"
        : "+f"(d[0]),"+f"(d[1]),"+f"(d[2]),"+f"(d[3])
        : "r"(a[0]),"r"(a[1]),"r"(a[2]),"r"(a[3]), "r"(b0),"r"(b1));
}

// ---------- scratch ----------
__device__ float g_xdown[NB*C*HD*HD];
__device__ float g_thin [NB*CC*HD*HD];
__device__ float g_g0   [NB*CC*1024];
__device__ float g_phi0 [NB*CC*1024];
__device__ float g_pool [3][NB*CC*85];
__device__ float g_ppc  [3][NB*85*16];
__device__ __align__(16) __nv_bfloat16 g_th_h [NB*4096*64];   // theta bf16 [n][q][64]
__device__ __align__(16) __nv_bfloat16 g_phi_h[NB*1024*64];   // phi bf16 [n][v][64]
__device__ __align__(16) __nv_bfloat16 g_gv_h [NB*1024*64];   // g bf16 [n][v][64]
__device__ float g_d1[NB*4096];
__device__ float g_d2[NB*1024];
__device__ float g_yatt[NB*4096*CC];
__device__ float g_z[NB*C*4096];

// ---------- K1: depthwise stride-4 4x4 conv ----------
__global__ void k_down(const float* __restrict__ x, const float* __restrict__ dw){
    int idx = blockIdx.x*blockDim.x + threadIdx.x;
    if (idx >= NB*C*HD*HD) return;
    int j = idx & 63, i = (idx>>6) & 63, nc = idx>>12;
    int ch = nc & (C-1);
    const float* xb = x + ((size_t)nc<<16) + i*4*256 + j*4;
    const float* w = dw + ch*16;
    float s = 0.f;
    #pragma unroll
    for (int a=0; a<4; a++){
        float4 v = *(const float4*)(xb + a*256);
        s += v.x*w[a*4+0] + v.y*w[a*4+1] + v.z*w[a*4+2] + v.w*w[a*4+3];
    }
    g_xdown[idx] = s;
}

// ---------- K2: theta 1x1 conv ----------
__global__ void k_conv_theta(const float* __restrict__ w, const float* __restrict__ b){
    __shared__ float xs[128][65];
    int bid = blockIdx.x;
    int n = bid >> 6; int t0 = (bid & 63) << 6;
    const float* xin = g_xdown + (size_t)n*C*4096;
    for (int idx = threadIdx.x; idx < 128*64; idx += 256){
        int cc_ = idx>>6, p = idx&63;
        xs[cc_][p] = xin[cc_*4096 + t0 + p];
    }
    __syncthreads();
    int o = threadIdx.x >> 2, grp = threadIdx.x & 3;
    const float* wo = w + o*128;
    float acc[16]; float bo = b[o];
    #pragma unroll
    for (int i=0;i<16;i++) acc[i] = bo;
    for (int c=0;c<128;c++){
        float wv = __ldg(&wo[c]);
        #pragma unroll
        for (int i=0;i<16;i++) acc[i] += wv * xs[c][grp*16+i];
    }
    float* op = g_thin + ((size_t)n*CC + o)*4096 + t0 + grp*16;
    #pragma unroll
    for (int i=0;i<16;i++) op[i] = acc[i];
}

// ---------- K3: fused g/phi conv + maxpool ----------
__global__ void k_conv_pool_gphi(const float* __restrict__ gw, const float* __restrict__ gb,
                                 const float* __restrict__ pw, const float* __restrict__ pb){
    __shared__ float xs[128][65];
    int bid = blockIdx.x;
    int n = bid >> 6; int tb = bid & 63; int by = tb>>3, bx = tb&7;
    const float* xin = g_xdown + (size_t)n*C*4096;
    int base = by*8*64 + bx*8;
    for (int idx = threadIdx.x; idx < 128*64; idx += 256){
        int c_ = idx>>6, p = idx&63;
        xs[c_][p] = xin[c_*4096 + base + (p>>3)*64 + (p&7)];
    }
    __syncthreads();
    int o = threadIdx.x >> 2, py = threadIdx.x & 3;
    float ga[16], pa[16];
    float gbi = gb[o], pbi = pb[o];
    #pragma unroll
    for (int i=0;i<16;i++){ ga[i]=gbi; pa[i]=pbi; }
    const float* gwo = gw + o*128;
    const float* pwo = pw + o*128;
    for (int c=0;c<128;c++){
        float wg = __ldg(&gwo[c]), wp = __ldg(&pwo[c]);
        #pragma unroll
        for (int i=0;i<16;i++){ float xv = xs[c][py*16+i]; ga[i]+=wg*xv; pa[i]+=wp*xv; }
    }
    int vy = by*4 + py;
    float* gout = g_g0  + ((size_t)n*CC+o)*1024 + vy*32 + bx*4;
    float* pout = g_phi0+ ((size_t)n*CC+o)*1024 + vy*32 + bx*4;
    #pragma unroll
    for (int px=0;px<4;px++){
        gout[px] = fmaxf(fmaxf(ga[2*px],ga[2*px+1]), fmaxf(ga[8+2*px],ga[8+2*px+1]));
        pout[px] = fmaxf(fmaxf(pa[2*px],pa[2*px+1]), fmaxf(pa[8+2*px],pa[8+2*px+1]));
    }
}

// ---------- K4: pyramid pools ----------
__global__ void k_pool(int br, int H){
    __shared__ float s8[64], s4[16], s2[4];
    int nc = blockIdx.x;
    const float* in = (br==0) ? g_g0 : (br==1) ? g_thin : g_phi0;
    const float* p = in + (size_t)nc*H*H;
    int t = threadIdx.x;
    int k0 = H >> 3;
    int cy = t>>3, cx = t&7;
    float s = 0.f;
    for (int a=0;a<k0;a++)
        for (int b2=0;b2<k0;b2++)
            s += p[(cy*k0+a)*H + cx*k0 + b2];
    s8[t] = s;
    __syncthreads();
    float* ob = g_pool[br] + nc*85;
    ob[t] = s8[t] / (float)(k0*k0);
    if (t < 16){
        int yy=t>>2, xx=t&3;
        float v = s8[(2*yy)*8+2*xx] + s8[(2*yy)*8+2*xx+1] + s8[(2*yy+1)*8+2*xx] + s8[(2*yy+1)*8+2*xx+1];
        s4[t]=v; ob[64+t] = v / (float)(4*k0*k0);
    }
    __syncthreads();
    if (t < 4){
        int yy=t>>1, xx=t&1;
        float v = s4[(2*yy)*4+2*xx] + s4[(2*yy)*4+2*xx+1] + s4[(2*yy+1)*4+2*xx] + s4[(2*yy+1)*4+2*xx+1];
        s2[t]=v; ob[80+t] = v / (float)(16*k0*k0);
    }
    __syncthreads();
    if (t == 0) ob[84] = (s2[0]+s2[1]+s2[2]+s2[3]) / (float)(64*k0*k0);
}

// ---------- K5: level convs ----------
__global__ void k_levelconv(int br, const float* __restrict__ pw,
                            const float* __restrict__ gamma, const float* __restrict__ beta){
    int idx = blockIdx.x*blockDim.x + threadIdx.x;
    if (idx >= NB*85*16) return;
    int o = idx & 15, s = (idx>>4) % 85, n = idx / (85*16);
    int lvl = (s<64) ? 0 : (s<80 ? 1 : (s<84 ? 2 : 3));
    const float* w = pw + (lvl*16+o)*64;
    const float* pl = g_pool[br] + n*64*85 + s;
    float acc = 0.f;
    for (int c=0;c<64;c++) acc += w[c]*pl[c*85];
    acc = acc*BN_INV*gamma[lvl*16+o] + beta[lvl*16+o];
    g_ppc[br][(n*85+s)*16+o] = fmaxf(acc, 0.f);
}

// ---------- K6: pyramid final conv -> bf16 ----------
__global__ void k_ppfinal(int br, const float* __restrict__ ow, const float* __restrict__ ob, int H){
    __shared__ float xs[64][65];
    __shared__ float us[64][65];
    int P = H*H;
    int bpn = P >> 6;
    int bid = blockIdx.x;
    int n = bid / bpn; int t0 = (bid % bpn) << 6;
    const float* X = (br==0) ? g_g0 : (br==1) ? g_thin : g_phi0;
    const float* xin = X + (size_t)n*CC*P;
    for (int idx = threadIdx.x; idx < 64*64; idx += 256){
        int c_ = idx>>6, p = idx&63;
        xs[c_][p] = xin[c_*P + t0 + p];
    }
    const float* pn = g_ppc[br] + n*85*16;
    float invH = 1.0f / (float)H;
    for (int e = threadIdx.x; e < 4096; e += 256){
        int p = e>>6, u = e&63;
        int lvl = u>>4, j = u&15;
        int pix = t0 + p; int y = pix / H, x = pix % H;
        int ps = 8 >> lvl;
        int off = (lvl==0) ? 0 : (lvl==1 ? 64 : (lvl==2 ? 80 : 84));
        float sy = fminf(fmaxf((y+0.5f)*ps*invH - 0.5f, 0.f), (float)(ps-1));
        float sx = fminf(fmaxf((x+0.5f)*ps*invH - 0.5f, 0.f), (float)(ps-1));
        int yl=(int)sy; int yh=min(yl+1, ps-1); float fy=sy-yl;
        int xl=(int)sx; int xh=min(xl+1, ps-1); float fx=sx-xl;
        const float* b00 = pn + (off + yl*ps + xl)*16;
        const float* b01 = pn + (off + yl*ps + xh)*16;
        const float* b10 = pn + (off + yh*ps + xl)*16;
        const float* b11 = pn + (off + yh*ps + xh)*16;
        us[p][u] = (b00[j]*(1.f-fx)+b01[j]*fx)*(1.f-fy) + (b10[j]*(1.f-fx)+b11[j]*fx)*fy;
    }
    __syncthreads();
    int o = threadIdx.x >> 2, grp = threadIdx.x & 3;
    const float* wo = ow + o*128;
    float acc[16]; float bo = ob[o];
    #pragma unroll
    for (int i=0;i<16;i++) acc[i]=bo;
    for (int c=0;c<64;c++){
        float wv = __ldg(&wo[c]);
        #pragma unroll
        for (int i=0;i<16;i++) acc[i] += wv*xs[c][grp*16+i];
    }
    for (int u=0;u<64;u++){
        float wv = __ldg(&wo[64+u]);
        #pragma unroll
        for (int i=0;i<16;i++) acc[i] += wv*us[grp*16+i][u];
    }
    #pragma unroll
    for (int i=0;i<16;i++){
        int pix = t0 + grp*16 + i;
        float v = acc[i];
        if (br == 1)      g_th_h [((size_t)n*4096 + pix)*64 + o] = __float2bfloat16(v);
        else if (br == 0) g_gv_h [((size_t)n*1024 + pix)*64 + o] = __float2bfloat16(v);
        else              g_phi_h[((size_t)n*1024 + pix)*64 + o] = __float2bfloat16(v);
    }
}

// ---------- K7: depth resizes ----------
__device__ __forceinline__ float bil256(const float* p, float sy, float sx){
    int yl=(int)sy; int yh=min(yl+1,255); float fy=sy-yl;
    int xl=(int)sx; int xh=min(xl+1,255); float fx=sx-xl;
    return (p[yl*256+xl]*(1.f-fx)+p[yl*256+xh]*fx)*(1.f-fy)
         + (p[yh*256+xl]*(1.f-fx)+p[yh*256+xh]*fx)*fy;
}
__global__ void k_depth(const float* __restrict__ dm){
    int idx = blockIdx.x*blockDim.x + threadIdx.x;
    const int T1 = NB*4096;
    if (idx < T1){
        int n = idx>>12; int q = idx & 4095; int yy = q>>6, xx = q&63;
        g_d1[idx] = bil256(dm + (size_t)n*65536, (float)(yy*255)/63.f, (float)(xx*255)/63.f);
    } else if (idx < T1 + NB*1024){
        int r = idx - T1; int n = r>>10; int q = r & 1023; int yy = q>>5, xx = q&31;
        g_d2[r] = bil256(dm + (size_t)n*65536, (float)(yy*255)/31.f, (float)(xx*255)/31.f);
    }
}

// ---------- K8: HMMA attention. grid=NB*32=128, 256 thr ----------
__global__ void __launch_bounds__(256,1) k_attn_hmma(){
    __shared__ __align__(16) __nv_bfloat16 sA[128*72];   // Q staging / phi chunks
    __shared__ __align__(16) __nv_bfloat16 sB[128*72];   // g chunks
    __shared__ float2 d2s[1024];                         // (d2, 1/(d2+eps))
    int tid = threadIdx.x, w = tid>>5, lane = tid&31;
    int n = blockIdx.x>>5, q0 = (blockIdx.x&31)*128;

    for (int i=tid;i<1024;i+=256){
        float d2 = g_d2[n*1024+i];
        d2s[i] = make_float2(d2, __fdividef(1.f, d2+EPS6));
    }
    const uint4* qg = (const uint4*)(g_th_h + ((size_t)(n*4096+q0))*64);
    for (int i=tid;i<1024;i+=256)
        *(uint4*)&sA[(i>>3)*72 + (i&7)*8] = qg[i];
    __syncthreads();
    uint32_t sAu = s2u(sA), sBu = s2u(sB);
    uint32_t aQ[4][4];
    {
        int arow = w*16 + (lane&15);
        int acol = (lane>>4)<<3;
        #pragma unroll
        for (int kb=0;kb<4;kb++)
            ldsm4(aQ[kb], sAu + (uint32_t)((arow*72 + kb*16 + acol)*2));
    }
    __syncthreads();

    int ra = lane>>2, colb = (lane&3)*2;
    int qa = q0 + w*16 + ra;
    float d1a = g_d1[n*4096+qa], d1b = g_d1[n*4096+qa+8];
    float ir1a = __fdividef(1.f,d1a+EPS6), ir1b = __fdividef(1.f,d1b+EPS6);
    int brow = (lane&7) + ((lane&16)?8:0);
    int bcol = (lane&8)?8:0;
    int grow = (lane&7) + ((lane&8)?8:0);
    int gcol = (lane&16)?8:0;
    const uint4* phg = (const uint4*)(g_phi_h + (size_t)n*65536);
    const uint4* gg  = (const uint4*)(g_gv_h + (size_t)n*65536);

    float m1a=-1e30f,s1a=0.f,m2a=-1e30f,s2a=0.f,mwa=-1e30f;
    float m1b=-1e30f,s1b=0.f,m2b=-1e30f,s2b=0.f,mwb=-1e30f;

    // ===== pass 1: stats =====
    for (int t=0;t<8;t++){
        for (int i=tid;i<1024;i+=256)
            *(uint4*)&sA[(i>>3)*72+(i&7)*8] = phg[t*1024+i];
        __syncthreads();
        float L[16][4];
        #pragma unroll
        for (int nt=0;nt<16;nt++){ L[nt][0]=0.f;L[nt][1]=0.f;L[nt][2]=0.f;L[nt][3]=0.f; }
        #pragma unroll
        for (int kb=0;kb<4;kb++){
            #pragma unroll
            for (int ng=0;ng<8;ng++){
                uint32_t bq[4];
                ldsm4(bq, sAu + (uint32_t)(((ng*16+brow)*72 + kb*16 + bcol)*2));
                mma16816(L[2*ng], aQ[kb], bq[0], bq[1]);
                mma16816(L[2*ng+1], aQ[kb], bq[2], bq[3]);
            }
        }
        float lma=-1e30f,lmb=-1e30f,rma=-1e30f,rmb=-1e30f;
        #pragma unroll
        for (int nt=0;nt<16;nt++){
            float2 dp = d2s[t*128+nt*8+colb];
            float2 dq = d2s[t*128+nt*8+colb+1];
            float r0 = fminf(d1a*dp.y, dp.x*ir1a);
            float r1 = fminf(d1a*dq.y, dq.x*ir1a);
            float r2 = fminf(d1b*dp.y, dp.x*ir1b);
            float r3 = fminf(d1b*dq.y, dq.x*ir1b);
            lma = fmaxf(lma, fmaxf(L[nt][0],L[nt][1]));
            lmb = fmaxf(lmb, fmaxf(L[nt][2],L[nt][3]));
            rma = fmaxf(rma, fmaxf(r0,r1));
            rmb = fmaxf(rmb, fmaxf(r2,r3));
            mwa = fmaxf(mwa, fmaxf(L[nt][0]+r0, L[nt][1]+r1));
            mwb = fmaxf(mwb, fmaxf(L[nt][2]+r2, L[nt][3]+r3));
        }
        float mn;
        mn = fmaxf(m1a,lma); s1a *= __expf(m1a-mn); m1a = mn;
        mn = fmaxf(m1b,lmb); s1b *= __expf(m1b-mn); m1b = mn;
        mn = fmaxf(m2a,rma); s2a *= __expf(m2a-mn); m2a = mn;
        mn = fmaxf(m2b,rmb); s2b *= __expf(m2b-mn); m2b = mn;
        #pragma unroll
        for (int nt=0;nt<16;nt++){
            float2 dp = d2s[t*128+nt*8+colb];
            float2 dq = d2s[t*128+nt*8+colb+1];
            float r0 = fminf(d1a*dp.y, dp.x*ir1a);
            float r1 = fminf(d1a*dq.y, dq.x*ir1a);
            float r2 = fminf(d1b*dp.y, dp.x*ir1b);
            float r3 = fminf(d1b*dq.y, dq.x*ir1b);
            s1a += __expf(L[nt][0]-m1a) + __expf(L[nt][1]-m1a);
            s1b += __expf(L[nt][2]-m1b) + __expf(L[nt][3]-m1b);
            s2a += __expf(r0-m2a) + __expf(r1-m2a);
            s2b += __expf(r2-m2b) + __expf(r3-m2b);
        }
        __syncthreads();
    }

    // quad reductions (lanes sharing a row: xor 1, 2)
    #pragma unroll
    for (int o=1;o<=2;o<<=1){
        float mo, so, mn;
        mo=__shfl_xor_sync(~0u,m1a,o); so=__shfl_xor_sync(~0u,s1a,o);
        mn=fmaxf(m1a,mo); s1a=s1a*__expf(m1a-mn)+so*__expf(mo-mn); m1a=mn;
        mo=__shfl_xor_sync(~0u,m1b,o); so=__shfl_xor_sync(~0u,s1b,o);
        mn=fmaxf(m1b,mo); s1b=s1b*__expf(m1b-mn)+so*__expf(mo-mn); m1b=mn;
        mo=__shfl_xor_sync(~0u,m2a,o); so=__shfl_xor_sync(~0u,s2a,o);
        mn=fmaxf(m2a,mo); s2a=s2a*__expf(m2a-mn)+so*__expf(mo-mn); m2a=mn;
        mo=__shfl_xor_sync(~0u,m2b,o); so=__shfl_xor_sync(~0u,s2b,o);
        mn=fmaxf(m2b,mo); s2b=s2b*__expf(m2b-mn)+so*__expf(mo-mn); m2b=mn;
        mwa=fmaxf(mwa,__shfl_xor_sync(~0u,mwa,o));
        mwb=fmaxf(mwb,__shfl_xor_sync(~0u,mwb,o));
    }
    float c1a=__fdividef(1.f,s1a*s2a), mm12a=m1a+m2a, amaxa=c1a*__expf(mwa-mm12a);
    float c1b=__fdividef(1.f,s1b*s2b), mm12b=m1b+m2b, amaxb=c1b*__expf(mwb-mm12b);

    // ===== pass 2: E + Y =====
    float Y[8][4];
    #pragma unroll
    for (int i=0;i<8;i++){ Y[i][0]=0.f;Y[i][1]=0.f;Y[i][2]=0.f;Y[i][3]=0.f; }
    float s3a=0.f, s3b=0.f;
    for (int t=0;t<8;t++){
        for (int i=tid;i<1024;i+=256)
            *(uint4*)&sA[(i>>3)*72+(i&7)*8] = phg[t*1024+i];
        for (int i=tid;i<1024;i+=256)
            *(uint4*)&sB[(i>>3)*72+(i&7)*8] = gg[t*1024+i];
        __syncthreads();
        float L[16][4];
        #pragma unroll
        for (int nt=0;nt<16;nt++){ L[nt][0]=0.f;L[nt][1]=0.f;L[nt][2]=0.f;L[nt][3]=0.f; }
        #pragma unroll
        for (int kb=0;kb<4;kb++){
            #pragma unroll
            for (int ng=0;ng<8;ng++){
                uint32_t bq[4];
                ldsm4(bq, sAu + (uint32_t)(((ng*16+brow)*72 + kb*16 + bcol)*2));
                mma16816(L[2*ng], aQ[kb], bq[0], bq[1]);
                mma16816(L[2*ng+1], aQ[kb], bq[2], bq[3]);
            }
        }
        uint32_t ek[8][4];
        #pragma unroll
        for (int nt=0;nt<16;nt++){
            float2 dp = d2s[t*128+nt*8+colb];
            float2 dq = d2s[t*128+nt*8+colb+1];
            float r0 = fminf(d1a*dp.y, dp.x*ir1a);
            float r1 = fminf(d1a*dq.y, dq.x*ir1a);
            float r2 = fminf(d1b*dp.y, dp.x*ir1b);
            float r3 = fminf(d1b*dq.y, dq.x*ir1b);
            float e0 = __expf(c1a*__expf(L[nt][0]+r0-mm12a)-amaxa);
            float e1 = __expf(c1a*__expf(L[nt][1]+r1-mm12a)-amaxa);
            float e2 = __expf(c1b*__expf(L[nt][2]+r2-mm12b)-amaxb);
            float e3 = __expf(c1b*__expf(L[nt][3]+r3-mm12b)-amaxb);
            s3a += e0+e1; s3b += e2+e3;
            __nv_bfloat162 pa = __floats2bfloat162_rn(e0,e1);
            __nv_bfloat162 pb = __floats2bfloat162_rn(e2,e3);
            int kb = nt>>1, hh = (nt&1)<<1;
            ek[kb][hh]   = *(uint32_t*)&pa;
            ek[kb][hh+1] = *(uint32_t*)&pb;
        }
        #pragma unroll
        for (int kb=0;kb<8;kb++){
            #pragma unroll
            for (int np=0;np<4;np++){
                uint32_t bg[4];
                ldsm4t(bg, sBu + (uint32_t)(((kb*16+grow)*72 + np*16 + gcol)*2));
                mma16816(Y[2*np], ek[kb], bg[0], bg[1]);
                mma16816(Y[2*np+1], ek[kb], bg[2], bg[3]);
            }
        }
        __syncthreads();
    }
    // s3 reduce + output
    s3a += __shfl_xor_sync(~0u,s3a,1); s3a += __shfl_xor_sync(~0u,s3a,2);
    s3b += __shfl_xor_sync(~0u,s3b,1); s3b += __shfl_xor_sync(~0u,s3b,2);
    float i3a = __fdividef(1.f,s3a), i3b = __fdividef(1.f,s3b);
    float* ya = g_yatt + ((size_t)(n*4096+qa))*64;
    float* yb = ya + 8*64;
    #pragma unroll
    for (int np2=0;np2<8;np2++){
        *(float2*)&ya[np2*8+colb] = make_float2(Y[np2][0]*i3a, Y[np2][1]*i3a);
        *(float2*)&yb[np2*8+colb] = make_float2(Y[np2][2]*i3b, Y[np2][3]*i3b);
    }
}

// ---------- K9: z conv ----------
__global__ void k_zconv(const float* __restrict__ zw, const float* __restrict__ zb){
    __shared__ float ys[64][65];
    int bid = blockIdx.x;
    int n = bid >> 6; int t0 = (bid & 63) << 6;
    const float* yb = g_yatt + ((size_t)n*4096 + t0)*64;
    for (int idx = threadIdx.x; idx < 4096; idx += 256)
        ys[idx>>6][idx&63] = yb[idx];
    __syncthreads();
    int o = threadIdx.x >> 1, grp = threadIdx.x & 1;
    const float* wo = zw + o*64;
    float bo = zb[o];
    float* zp = g_z + ((size_t)n*C + o)*4096 + t0 + grp*32;
    for (int p=0;p<32;p++){
        float acc = bo;
        const float* yr = &ys[grp*32+p][0];
        #pragma unroll
        for (int c=0;c<64;c++) acc += __ldg(&wo[c])*yr[c];
        zp[p] = acc;
    }
}

// ---------- K10: epilogue ----------
__global__ void k_epi(const float* __restrict__ x, float* __restrict__ out){
    int idx = blockIdx.x*blockDim.x + threadIdx.x;
    if (idx >= NB*C*H0*H0) return;
    int X_ = idx & 255, Y = (idx>>8) & 255, nch = idx >> 16;
    float sy = (float)(Y*63)/255.f, sx = (float)(X_*63)/255.f;
    int yl=(int)sy, xl=(int)sx;
    int yh=min(yl+1,63), xh=min(xl+1,63);
    float fy=sy-yl, fx=sx-xl;
    const float* zp = g_z + (size_t)nch*4096;
    float v = (zp[yl*64+xl]*(1.f-fx)+zp[yl*64+xh]*fx)*(1.f-fy)
            + (zp[yh*64+xl]*(1.f-fx)+zp[yh*64+xh]*fx)*fy;
    out[idx] = x[idx] + v;
}

// ---------- host ----------
extern "C" void kernel_launch(void* const* d_in, const int* in_sizes, int n_in,
                              void* d_out, int out_size){
    const float* x       = (const float*)d_in[0];
    const float* depth   = (const float*)d_in[1];
    const float* down_w  = (const float*)d_in[2];
    const float* theta_w = (const float*)d_in[3];
    const float* theta_b = (const float*)d_in[4];
    const float* phi_w   = (const float*)d_in[5];
    const float* phi_b   = (const float*)d_in[6];
    const float* g_w     = (const float*)d_in[7];
    const float* g_b     = (const float*)d_in[8];
    const float* z_w     = (const float*)d_in[9];
    const float* z_b     = (const float*)d_in[10];
    const float* ppg_pw  = (const float*)d_in[11];
    const float* ppg_gam = (const float*)d_in[12];
    const float* ppg_bet = (const float*)d_in[13];
    const float* ppg_ow  = (const float*)d_in[14];
    const float* ppg_ob  = (const float*)d_in[15];
    const float* ppt_pw  = (const float*)d_in[16];
    const float* ppt_gam = (const float*)d_in[17];
    const float* ppt_bet = (const float*)d_in[18];
    const float* ppt_ow  = (const float*)d_in[19];
    const float* ppt_ob  = (const float*)d_in[20];
    const float* ppp_pw  = (const float*)d_in[21];
    const float* ppp_gam = (const float*)d_in[22];
    const float* ppp_bet = (const float*)d_in[23];
    const float* ppp_ow  = (const float*)d_in[24];
    const float* ppp_ob  = (const float*)d_in[25];
    float* out = (float*)d_out;

    k_down<<<(NB*C*HD*HD + 255)/256, 256>>>(x, down_w);
    k_conv_theta<<<NB*64, 256>>>(theta_w, theta_b);
    k_conv_pool_gphi<<<NB*64, 256>>>(g_w, g_b, phi_w, phi_b);
    k_pool<<<NB*64, 64>>>(0, 32);
    k_pool<<<NB*64, 64>>>(1, 64);
    k_pool<<<NB*64, 64>>>(2, 32);
    int lc_grid = (NB*85*16 + 255)/256;
    k_levelconv<<<lc_grid, 256>>>(0, ppg_pw, ppg_gam, ppg_bet);
    k_levelconv<<<lc_grid, 256>>>(1, ppt_pw, ppt_gam, ppt_bet);
    k_levelconv<<<lc_grid, 256>>>(2, ppp_pw, ppp_gam, ppp_bet);
    k_ppfinal<<<NB*(1024/64), 256>>>(0, ppg_ow, ppg_ob, 32);
    k_ppfinal<<<NB*(4096/64), 256>>>(1, ppt_ow, ppt_ob, 64);
    k_ppfinal<<<NB*(1024/64), 256>>>(2, ppp_ow, ppp_ob, 32);
    k_depth<<<(NB*4096 + NB*1024 + 255)/256, 256>>>(depth);
    k_attn_hmma<<<NB*32, 256>>>();
    k_zconv<<<NB*64, 256>>>(z_w, z_b);
    k_epi<<<(NB*C*H0*H0 + 255)/256, 256>>>(x, out);
}

// round 5
// speedup vs baseline: 2.2057x; 1.2375x over previous
#include <cuda_runtime.h>
#include <cuda_bf16.h>
#include <math.h>
#include <cstdint>

#define NB 4
#define C 128
#define CC 64
#define H0 256
#define HD 64
#define EPS6 1e-6f
#define BN_INV 0.9999950000374997f

// ---------- helpers ----------
__device__ __forceinline__ uint32_t s2u(const void* p){
    uint32_t a; asm("{ .reg .u64 t; cvta.to.shared.u64 t, %1; cvt.u32.u64 %0, t; }" : "=r"(a) : "l"(p)); return a;
}
__device__ __forceinline__ void ldsm4(uint32_t* r, uint32_t a){
    asm volatile("ldmatrix.sync.aligned.m8n8.x4.shared.b16 {%0,%1,%2,%3}, [%4];"
        : "=r"(r[0]),"=r"(r[1]),"=r"(r[2]),"=r"(r[3]) : "r"(a));
}
__device__ __forceinline__ void ldsm4t(uint32_t* r, uint32_t a){
    asm volatile("ldmatrix.sync.aligned.m8n8.x4.trans.shared.b16 {%0,%1,%2,%3}, [%4];"
        : "=r"(r[0]),"=r"(r[1]),"=r"(r[2]),"=r"(r[3]) : "r"(a));
}
__device__ __forceinline__ void mma16816(float* d, const uint32_t* a, uint32_t b0, uint32_t b1){
    asm volatile("mma.sync.aligned.m16n8k16.row.col.f32.bf16.bf16.f32 "
        "{%0,%1,%2,%3}, {%4,%5,%6,%7}, {%8,%9}, {%0,%1,%2,%3};"
        : "+f"(d[0]),"+f"(d[1]),"+f"(d[2]),"+f"(d[3])
        : "r"(a[0]),"r"(a[1]),"r"(a[2]),"r"(a[3]), "r"(b0),"r"(b1));
}
// exp(x) for x in [-1, 1]: half-and-square, Taylor deg 6, rel err < 6e-6. Pure FMA.
__device__ __forceinline__ float expp(float x){
    float h = 0.5f*x;
    float p = __fmaf_rn(h, 0.0013888889f, 0.0083333333f);
    p = __fmaf_rn(h, p, 0.0416666667f);
    p = __fmaf_rn(h, p, 0.1666666667f);
    p = __fmaf_rn(h, p, 0.5f);
    p = __fmaf_rn(h, p, 1.0f);
    p = __fmaf_rn(h, p, 1.0f);
    return p*p;
}

// ---------- scratch ----------
__device__ float g_xdown[NB*C*HD*HD];
__device__ float g_thin [NB*CC*HD*HD];
__device__ float g_g0   [NB*CC*1024];
__device__ float g_phi0 [NB*CC*1024];
__device__ float g_pool [3][NB*CC*85];
__device__ float g_ppc  [3][NB*85*16];
__device__ __align__(16) __nv_bfloat16 g_th_h [NB*4096*64];
__device__ __align__(16) __nv_bfloat16 g_phi_h[NB*1024*64];
__device__ __align__(16) __nv_bfloat16 g_gv_h [NB*1024*64];
__device__ float g_d1[NB*4096];
__device__ float g_d2[NB*1024];
__device__ float g_yatt[NB*4096*CC];
__device__ float g_z[NB*C*4096];

// ---------- K1: depthwise stride-4 4x4 conv ----------
__global__ void k_down(const float* __restrict__ x, const float* __restrict__ dw){
    int idx = blockIdx.x*blockDim.x + threadIdx.x;
    if (idx >= NB*C*HD*HD) return;
    int j = idx & 63, i = (idx>>6) & 63, nc = idx>>12;
    int ch = nc & (C-1);
    const float* xb = x + ((size_t)nc<<16) + i*4*256 + j*4;
    const float* w = dw + ch*16;
    float s = 0.f;
    #pragma unroll
    for (int a=0; a<4; a++){
        float4 v = *(const float4*)(xb + a*256);
        s += v.x*w[a*4+0] + v.y*w[a*4+1] + v.z*w[a*4+2] + v.w*w[a*4+3];
    }
    g_xdown[idx] = s;
}

// ---------- K2: theta 1x1 conv ----------
__global__ void k_conv_theta(const float* __restrict__ w, const float* __restrict__ b){
    __shared__ float xs[128][65];
    int bid = blockIdx.x;
    int n = bid >> 6; int t0 = (bid & 63) << 6;
    const float* xin = g_xdown + (size_t)n*C*4096;
    for (int idx = threadIdx.x; idx < 128*64; idx += 256){
        int cc_ = idx>>6, p = idx&63;
        xs[cc_][p] = xin[cc_*4096 + t0 + p];
    }
    __syncthreads();
    int o = threadIdx.x >> 2, grp = threadIdx.x & 3;
    const float* wo = w + o*128;
    float acc[16]; float bo = b[o];
    #pragma unroll
    for (int i=0;i<16;i++) acc[i] = bo;
    for (int c=0;c<128;c++){
        float wv = __ldg(&wo[c]);
        #pragma unroll
        for (int i=0;i<16;i++) acc[i] += wv * xs[c][grp*16+i];
    }
    float* op = g_thin + ((size_t)n*CC + o)*4096 + t0 + grp*16;
    #pragma unroll
    for (int i=0;i<16;i++) op[i] = acc[i];
}

// ---------- K3: fused g/phi conv + maxpool ----------
__global__ void k_conv_pool_gphi(const float* __restrict__ gw, const float* __restrict__ gb,
                                 const float* __restrict__ pw, const float* __restrict__ pb){
    __shared__ float xs[128][65];
    int bid = blockIdx.x;
    int n = bid >> 6; int tb = bid & 63; int by = tb>>3, bx = tb&7;
    const float* xin = g_xdown + (size_t)n*C*4096;
    int base = by*8*64 + bx*8;
    for (int idx = threadIdx.x; idx < 128*64; idx += 256){
        int c_ = idx>>6, p = idx&63;
        xs[c_][p] = xin[c_*4096 + base + (p>>3)*64 + (p&7)];
    }
    __syncthreads();
    int o = threadIdx.x >> 2, py = threadIdx.x & 3;
    float ga[16], pa[16];
    float gbi = gb[o], pbi = pb[o];
    #pragma unroll
    for (int i=0;i<16;i++){ ga[i]=gbi; pa[i]=pbi; }
    const float* gwo = gw + o*128;
    const float* pwo = pw + o*128;
    for (int c=0;c<128;c++){
        float wg = __ldg(&gwo[c]), wp = __ldg(&pwo[c]);
        #pragma unroll
        for (int i=0;i<16;i++){ float xv = xs[c][py*16+i]; ga[i]+=wg*xv; pa[i]+=wp*xv; }
    }
    int vy = by*4 + py;
    float* gout = g_g0  + ((size_t)n*CC+o)*1024 + vy*32 + bx*4;
    float* pout = g_phi0+ ((size_t)n*CC+o)*1024 + vy*32 + bx*4;
    #pragma unroll
    for (int px=0;px<4;px++){
        gout[px] = fmaxf(fmaxf(ga[2*px],ga[2*px+1]), fmaxf(ga[8+2*px],ga[8+2*px+1]));
        pout[px] = fmaxf(fmaxf(pa[2*px],pa[2*px+1]), fmaxf(pa[8+2*px],pa[8+2*px+1]));
    }
}

// ---------- K4: pyramid pools (all 3 branches in one grid) ----------
__global__ void k_pool_all(){
    __shared__ float s8[64], s4[16], s2[4];
    int bid = blockIdx.x;                 // 3*NB*64
    int br = bid >> 8; int nc = bid & 255;
    int H = (br==1) ? 64 : 32;
    const float* in = (br==0) ? g_g0 : (br==1) ? g_thin : g_phi0;
    const float* p = in + (size_t)nc*H*H;
    int t = threadIdx.x;
    int k0 = H >> 3;
    int cy = t>>3, cx = t&7;
    const float* cell = p + (cy*k0)*H + cx*k0;
    float s = 0.f;
    if (k0 == 8){
        #pragma unroll
        for (int a=0;a<8;a++){
            float4 v1 = *(const float4*)(cell + a*64);
            float4 v2 = *(const float4*)(cell + a*64 + 4);
            s += v1.x+v1.y+v1.z+v1.w + v2.x+v2.y+v2.z+v2.w;
        }
    } else {
        #pragma unroll
        for (int a=0;a<4;a++){
            float4 v = *(const float4*)(cell + a*32);
            s += v.x+v.y+v.z+v.w;
        }
    }
    s8[t] = s;
    __syncthreads();
    float* ob = g_pool[br] + nc*85;
    ob[t] = s8[t] / (float)(k0*k0);
    if (t < 16){
        int yy=t>>2, xx=t&3;
        float v = s8[(2*yy)*8+2*xx] + s8[(2*yy)*8+2*xx+1] + s8[(2*yy+1)*8+2*xx] + s8[(2*yy+1)*8+2*xx+1];
        s4[t]=v; ob[64+t] = v / (float)(4*k0*k0);
    }
    __syncthreads();
    if (t < 4){
        int yy=t>>1, xx=t&1;
        float v = s4[(2*yy)*4+2*xx] + s4[(2*yy)*4+2*xx+1] + s4[(2*yy+1)*4+2*xx] + s4[(2*yy+1)*4+2*xx+1];
        s2[t]=v; ob[80+t] = v / (float)(16*k0*k0);
    }
    __syncthreads();
    if (t == 0) ob[84] = (s2[0]+s2[1]+s2[2]+s2[3]) / (float)(64*k0*k0);
}

// ---------- K5: level convs (all 3 branches) ----------
__global__ void k_levelconv_all(const float* __restrict__ pw0, const float* __restrict__ g0, const float* __restrict__ b0,
                                const float* __restrict__ pw1, const float* __restrict__ g1, const float* __restrict__ b1,
                                const float* __restrict__ pw2, const float* __restrict__ g2, const float* __restrict__ b2){
    int idx = blockIdx.x*blockDim.x + threadIdx.x;
    if (idx >= 3*NB*85*16) return;
    int br = idx / (NB*85*16);
    int rem = idx % (NB*85*16);
    int o = rem & 15, s = (rem>>4) % 85, n = rem / (85*16);
    const float* pw = (br==0)?pw0:(br==1)?pw1:pw2;
    const float* gamma = (br==0)?g0:(br==1)?g1:g2;
    const float* beta = (br==0)?b0:(br==1)?b1:b2;
    int lvl = (s<64) ? 0 : (s<80 ? 1 : (s<84 ? 2 : 3));
    const float* w = pw + (lvl*16+o)*64;
    const float* pl = g_pool[br] + n*64*85 + s;
    float acc = 0.f;
    for (int c=0;c<64;c++) acc += w[c]*pl[c*85];
    acc = acc*BN_INV*gamma[lvl*16+o] + beta[lvl*16+o];
    g_ppc[br][(n*85+s)*16+o] = fmaxf(acc, 0.f);
}

// ---------- K6: pyramid final conv -> bf16 ----------
__global__ void k_ppfinal(int br, const float* __restrict__ ow, const float* __restrict__ ob, int H){
    __shared__ float xs[64][65];
    __shared__ float us[64][65];
    int P = H*H;
    int bpn = P >> 6;
    int bid = blockIdx.x;
    int n = bid / bpn; int t0 = (bid % bpn) << 6;
    const float* X = (br==0) ? g_g0 : (br==1) ? g_thin : g_phi0;
    const float* xin = X + (size_t)n*CC*P;
    for (int idx = threadIdx.x; idx < 64*64; idx += 256){
        int c_ = idx>>6, p = idx&63;
        xs[c_][p] = xin[c_*P + t0 + p];
    }
    const float* pn = g_ppc[br] + n*85*16;
    float invH = 1.0f / (float)H;
    for (int e = threadIdx.x; e < 4096; e += 256){
        int p = e>>6, u = e&63;
        int lvl = u>>4, j = u&15;
        int pix = t0 + p; int y = pix / H, x = pix % H;
        int ps = 8 >> lvl;
        int off = (lvl==0) ? 0 : (lvl==1 ? 64 : (lvl==2 ? 80 : 84));
        float sy = fminf(fmaxf((y+0.5f)*ps*invH - 0.5f, 0.f), (float)(ps-1));
        float sx = fminf(fmaxf((x+0.5f)*ps*invH - 0.5f, 0.f), (float)(ps-1));
        int yl=(int)sy; int yh=min(yl+1, ps-1); float fy=sy-yl;
        int xl=(int)sx; int xh=min(xl+1, ps-1); float fx=sx-xl;
        const float* b00 = pn + (off + yl*ps + xl)*16;
        const float* b01 = pn + (off + yl*ps + xh)*16;
        const float* b10 = pn + (off + yh*ps + xl)*16;
        const float* b11 = pn + (off + yh*ps + xh)*16;
        us[p][u] = (b00[j]*(1.f-fx)+b01[j]*fx)*(1.f-fy) + (b10[j]*(1.f-fx)+b11[j]*fx)*fy;
    }
    __syncthreads();
    int o = threadIdx.x >> 2, grp = threadIdx.x & 3;
    const float* wo = ow + o*128;
    float acc[16]; float bo = ob[o];
    #pragma unroll
    for (int i=0;i<16;i++) acc[i]=bo;
    for (int c=0;c<64;c++){
        float wv = __ldg(&wo[c]);
        #pragma unroll
        for (int i=0;i<16;i++) acc[i] += wv*xs[c][grp*16+i];
    }
    for (int u=0;u<64;u++){
        float wv = __ldg(&wo[64+u]);
        #pragma unroll
        for (int i=0;i<16;i++) acc[i] += wv*us[grp*16+i][u];
    }
    #pragma unroll
    for (int i=0;i<16;i++){
        int pix = t0 + grp*16 + i;
        float v = acc[i];
        if (br == 1)      g_th_h [((size_t)n*4096 + pix)*64 + o] = __float2bfloat16(v);
        else if (br == 0) g_gv_h [((size_t)n*1024 + pix)*64 + o] = __float2bfloat16(v);
        else              g_phi_h[((size_t)n*1024 + pix)*64 + o] = __float2bfloat16(v);
    }
}

// ---------- K7: depth resizes ----------
__device__ __forceinline__ float bil256(const float* p, float sy, float sx){
    int yl=(int)sy; int yh=min(yl+1,255); float fy=sy-yl;
    int xl=(int)sx; int xh=min(xl+1,255); float fx=sx-xl;
    return (p[yl*256+xl]*(1.f-fx)+p[yl*256+xh]*fx)*(1.f-fy)
         + (p[yh*256+xl]*(1.f-fx)+p[yh*256+xh]*fx)*fy;
}
__global__ void k_depth(const float* __restrict__ dm){
    int idx = blockIdx.x*blockDim.x + threadIdx.x;
    const int T1 = NB*4096;
    if (idx < T1){
        int n = idx>>12; int q = idx & 4095; int yy = q>>6, xx = q&63;
        g_d1[idx] = bil256(dm + (size_t)n*65536, (float)(yy*255)/63.f, (float)(xx*255)/63.f);
    } else if (idx < T1 + NB*1024){
        int r = idx - T1; int n = r>>10; int q = r & 1023; int yy = q>>5, xx = q&31;
        g_d2[r] = bil256(dm + (size_t)n*65536, (float)(yy*255)/31.f, (float)(xx*255)/31.f);
    }
}

// ---------- K8: HMMA attention, MUFU-light. grid=NB*32=128, 256 thr ----------
__global__ void __launch_bounds__(256,1) k_attn_hmma(){
    __shared__ __align__(16) __nv_bfloat16 sA[128*72];
    __shared__ __align__(16) __nv_bfloat16 sB[128*72];
    __shared__ float2 d2s[1024];
    int tid = threadIdx.x, w = tid>>5, lane = tid&31;
    int n = blockIdx.x>>5, q0 = (blockIdx.x&31)*128;

    for (int i=tid;i<1024;i+=256){
        float d2 = g_d2[n*1024+i];
        d2s[i] = make_float2(d2, __fdividef(1.f, d2+EPS6));
    }
    const uint4* qg = (const uint4*)(g_th_h + ((size_t)(n*4096+q0))*64);
    for (int i=tid;i<1024;i+=256)
        *(uint4*)&sA[(i>>3)*72 + (i&7)*8] = qg[i];
    __syncthreads();
    uint32_t sAu = s2u(sA), sBu = s2u(sB);
    uint32_t aQ[4][4];
    {
        int arow = w*16 + (lane&15);
        int acol = (lane>>4)<<3;
        #pragma unroll
        for (int kb=0;kb<4;kb++)
            ldsm4(aQ[kb], sAu + (uint32_t)((arow*72 + kb*16 + acol)*2));
    }
    __syncthreads();

    int ra = lane>>2, colb = (lane&3)*2;
    int qa = q0 + w*16 + ra;
    float d1a = g_d1[n*4096+qa], d1b = g_d1[n*4096+qa+8];
    float ir1a = __fdividef(1.f,d1a+EPS6), ir1b = __fdividef(1.f,d1b+EPS6);
    int brow = (lane&7) + ((lane&16)?8:0);
    int bcol = (lane&8)?8:0;
    int grow = (lane&7) + ((lane&8)?8:0);
    int gcol = (lane&16)?8:0;
    const uint4* phg = (const uint4*)(g_phi_h + (size_t)n*65536);
    const uint4* gg  = (const uint4*)(g_gv_h + (size_t)n*65536);

    float m1a=-1e30f,s1a=0.f,m2a=-1e30f,s2a=0.f;
    float m1b=-1e30f,s1b=0.f,m2b=-1e30f,s2b=0.f;

    // ===== pass 1: stats. s2 uses fixed ref exp(r-1) via FMA poly; s1 online with expf =====
    for (int t=0;t<8;t++){
        for (int i=tid;i<1024;i+=256)
            *(uint4*)&sA[(i>>3)*72+(i&7)*8] = phg[t*1024+i];
        __syncthreads();
        float L[16][4];
        #pragma unroll
        for (int nt=0;nt<16;nt++){ L[nt][0]=0.f;L[nt][1]=0.f;L[nt][2]=0.f;L[nt][3]=0.f; }
        #pragma unroll
        for (int kb=0;kb<4;kb++){
            #pragma unroll
            for (int ng=0;ng<8;ng++){
                uint32_t bq[4];
                ldsm4(bq, sAu + (uint32_t)(((ng*16+brow)*72 + kb*16 + bcol)*2));
                mma16816(L[2*ng], aQ[kb], bq[0], bq[1]);
                mma16816(L[2*ng+1], aQ[kb], bq[2], bq[3]);
            }
        }
        float lma=-1e30f,lmb=-1e30f;
        #pragma unroll
        for (int nt=0;nt<16;nt++){
            float2 dp = d2s[t*128+nt*8+colb];
            float2 dq = d2s[t*128+nt*8+colb+1];
            float r0 = fminf(d1a*dp.y, dp.x*ir1a);
            float r1 = fminf(d1a*dq.y, dq.x*ir1a);
            float r2 = fminf(d1b*dp.y, dp.x*ir1b);
            float r3 = fminf(d1b*dq.y, dq.x*ir1b);
            m2a = fmaxf(m2a, fmaxf(r0,r1));
            m2b = fmaxf(m2b, fmaxf(r2,r3));
            s2a += expp(r0-1.f) + expp(r1-1.f);
            s2b += expp(r2-1.f) + expp(r3-1.f);
            lma = fmaxf(lma, fmaxf(L[nt][0],L[nt][1]));
            lmb = fmaxf(lmb, fmaxf(L[nt][2],L[nt][3]));
        }
        float mn;
        mn = fmaxf(m1a,lma); s1a *= __expf(m1a-mn); m1a = mn;
        mn = fmaxf(m1b,lmb); s1b *= __expf(m1b-mn); m1b = mn;
        #pragma unroll
        for (int nt=0;nt<16;nt++){
            s1a += __expf(L[nt][0]-m1a) + __expf(L[nt][1]-m1a);
            s1b += __expf(L[nt][2]-m1b) + __expf(L[nt][3]-m1b);
        }
        __syncthreads();
    }

    // quad reductions (lanes sharing a row: xor 1, 2)
    #pragma unroll
    for (int o=1;o<=2;o<<=1){
        float mo, so, mn;
        mo=__shfl_xor_sync(~0u,m1a,o); so=__shfl_xor_sync(~0u,s1a,o);
        mn=fmaxf(m1a,mo); s1a=s1a*__expf(m1a-mn)+so*__expf(mo-mn); m1a=mn;
        mo=__shfl_xor_sync(~0u,m1b,o); so=__shfl_xor_sync(~0u,s1b,o);
        mn=fmaxf(m1b,mo); s1b=s1b*__expf(m1b-mn)+so*__expf(mo-mn); m1b=mn;
        s2a += __shfl_xor_sync(~0u,s2a,o);
        s2b += __shfl_xor_sync(~0u,s2b,o);
        m2a = fmaxf(m2a,__shfl_xor_sync(~0u,m2a,o));
        m2b = fmaxf(m2b,__shfl_xor_sync(~0u,m2b,o));
    }
    // S2 = sum exp(r - M2) = e^{1-M2} * sum exp(r-1);  1-M2 in [0,1) -> poly
    float S2a = s2a * expp(1.f - m2a);
    float S2b = s2b * expp(1.f - m2b);
    float c1a=__fdividef(1.f,s1a*S2a), mm12a=m1a+m2a;
    float c1b=__fdividef(1.f,s1b*S2b), mm12b=m1b+m2b;

    // ===== pass 2: E + Y. outer exp is poly (arg = Ra*Rd in [0,1]) =====
    float Y[8][4];
    #pragma unroll
    for (int i=0;i<8;i++){ Y[i][0]=0.f;Y[i][1]=0.f;Y[i][2]=0.f;Y[i][3]=0.f; }
    float s3a=0.f, s3b=0.f;
    for (int t=0;t<8;t++){
        for (int i=tid;i<1024;i+=256)
            *(uint4*)&sA[(i>>3)*72+(i&7)*8] = phg[t*1024+i];
        for (int i=tid;i<1024;i+=256)
            *(uint4*)&sB[(i>>3)*72+(i&7)*8] = gg[t*1024+i];
        __syncthreads();
        float L[16][4];
        #pragma unroll
        for (int nt=0;nt<16;nt++){ L[nt][0]=0.f;L[nt][1]=0.f;L[nt][2]=0.f;L[nt][3]=0.f; }
        #pragma unroll
        for (int kb=0;kb<4;kb++){
            #pragma unroll
            for (int ng=0;ng<8;ng++){
                uint32_t bq[4];
                ldsm4(bq, sAu + (uint32_t)(((ng*16+brow)*72 + kb*16 + bcol)*2));
                mma16816(L[2*ng], aQ[kb], bq[0], bq[1]);
                mma16816(L[2*ng+1], aQ[kb], bq[2], bq[3]);
            }
        }
        uint32_t ek[8][4];
        #pragma unroll
        for (int nt=0;nt<16;nt++){
            float2 dp = d2s[t*128+nt*8+colb];
            float2 dq = d2s[t*128+nt*8+colb+1];
            float r0 = fminf(d1a*dp.y, dp.x*ir1a);
            float r1 = fminf(d1a*dq.y, dq.x*ir1a);
            float r2 = fminf(d1b*dp.y, dp.x*ir1b);
            float r3 = fminf(d1b*dq.y, dq.x*ir1b);
            float e0 = expp(c1a*__expf(L[nt][0]+r0-mm12a));
            float e1 = expp(c1a*__expf(L[nt][1]+r1-mm12a));
            float e2 = expp(c1b*__expf(L[nt][2]+r2-mm12b));
            float e3 = expp(c1b*__expf(L[nt][3]+r3-mm12b));
            s3a += e0+e1; s3b += e2+e3;
            __nv_bfloat162 pa = __floats2bfloat162_rn(e0,e1);
            __nv_bfloat162 pb = __floats2bfloat162_rn(e2,e3);
            int kb = nt>>1, hh = (nt&1)<<1;
            ek[kb][hh]   = *(uint32_t*)&pa;
            ek[kb][hh+1] = *(uint32_t*)&pb;
        }
        #pragma unroll
        for (int kb=0;kb<8;kb++){
            #pragma unroll
            for (int np=0;np<4;np++){
                uint32_t bg[4];
                ldsm4t(bg, sBu + (uint32_t)(((kb*16+grow)*72 + np*16 + gcol)*2));
                mma16816(Y[2*np], ek[kb], bg[0], bg[1]);
                mma16816(Y[2*np+1], ek[kb], bg[2], bg[3]);
            }
        }
        __syncthreads();
    }
    s3a += __shfl_xor_sync(~0u,s3a,1); s3a += __shfl_xor_sync(~0u,s3a,2);
    s3b += __shfl_xor_sync(~0u,s3b,1); s3b += __shfl_xor_sync(~0u,s3b,2);
    float i3a = __fdividef(1.f,s3a), i3b = __fdividef(1.f,s3b);
    float* ya = g_yatt + ((size_t)(n*4096+qa))*64;
    float* yb = ya + 8*64;
    #pragma unroll
    for (int np2=0;np2<8;np2++){
        *(float2*)&ya[np2*8+colb] = make_float2(Y[np2][0]*i3a, Y[np2][1]*i3a);
        *(float2*)&yb[np2*8+colb] = make_float2(Y[np2][2]*i3b, Y[np2][3]*i3b);
    }
}

// ---------- K9: z conv (weights preloaded in regs, vectorized smem reads) ----------
__global__ void k_zconv(const float* __restrict__ zw, const float* __restrict__ zb){
    __shared__ float ys[64][68];
    int bid = blockIdx.x;
    int n = bid >> 6; int t0 = (bid & 63) << 6;
    const float* yb = g_yatt + ((size_t)n*4096 + t0)*64;
    for (int idx = threadIdx.x; idx < 4096; idx += 256)
        ys[idx>>6][idx&63] = yb[idx];
    __syncthreads();
    int o = threadIdx.x >> 1, grp = threadIdx.x & 1;
    float4 wreg[16];
    const float4* wo4 = (const float4*)(zw + o*64);
    #pragma unroll
    for (int i=0;i<16;i++) wreg[i] = __ldg(&wo4[i]);
    float bo = zb[o];
    float* zp = g_z + ((size_t)n*C + o)*4096 + t0 + grp*32;
    #pragma unroll 4
    for (int p=0;p<32;p++){
        const float4* yr = (const float4*)&ys[grp*32+p][0];
        float acc = bo;
        #pragma unroll
        for (int i=0;i<16;i++){
            float4 v = yr[i];
            acc += wreg[i].x*v.x + wreg[i].y*v.y + wreg[i].z*v.z + wreg[i].w*v.w;
        }
        zp[p] = acc;
    }
}

// ---------- K10: epilogue (4 px/thread, float4) ----------
__global__ void k_epi(const float* __restrict__ x, float* __restrict__ out){
    int idx = blockIdx.x*blockDim.x + threadIdx.x;
    if (idx >= NB*C*H0*H0/4) return;
    int xb4 = (idx & 63) << 2;
    int Y = (idx>>6) & 255;
    int nch = idx >> 14;
    float sy = (float)(Y*63)/255.f;
    int yl=(int)sy; int yh=min(yl+1,63); float fy=sy-yl;
    const float* z0 = g_z + (size_t)nch*4096 + yl*64;
    const float* z1 = g_z + (size_t)nch*4096 + yh*64;
    float4 r;
    float* rp = &r.x;
    #pragma unroll
    for (int k=0;k<4;k++){
        int X_ = xb4 + k;
        float sx = (float)(X_*63)/255.f;
        int xl=(int)sx; int xh=min(xl+1,63); float fx=sx-xl;
        rp[k] = (z0[xl]*(1.f-fx)+z0[xh]*fx)*(1.f-fy)
              + (z1[xl]*(1.f-fx)+z1[xh]*fx)*fy;
    }
    float4 xin = *(const float4*)(x + ((size_t)idx<<2));
    r.x += xin.x; r.y += xin.y; r.z += xin.z; r.w += xin.w;
    *(float4*)(out + ((size_t)idx<<2)) = r;
}

// ---------- host ----------
extern "C" void kernel_launch(void* const* d_in, const int* in_sizes, int n_in,
                              void* d_out, int out_size){
    const float* x       = (const float*)d_in[0];
    const float* depth   = (const float*)d_in[1];
    const float* down_w  = (const float*)d_in[2];
    const float* theta_w = (const float*)d_in[3];
    const float* theta_b = (const float*)d_in[4];
    const float* phi_w   = (const float*)d_in[5];
    const float* phi_b   = (const float*)d_in[6];
    const float* g_w     = (const float*)d_in[7];
    const float* g_b     = (const float*)d_in[8];
    const float* z_w     = (const float*)d_in[9];
    const float* z_b     = (const float*)d_in[10];
    const float* ppg_pw  = (const float*)d_in[11];
    const float* ppg_gam = (const float*)d_in[12];
    const float* ppg_bet = (const float*)d_in[13];
    const float* ppg_ow  = (const float*)d_in[14];
    const float* ppg_ob  = (const float*)d_in[15];
    const float* ppt_pw  = (const float*)d_in[16];
    const float* ppt_gam = (const float*)d_in[17];
    const float* ppt_bet = (const float*)d_in[18];
    const float* ppt_ow  = (const float*)d_in[19];
    const float* ppt_ob  = (const float*)d_in[20];
    const float* ppp_pw  = (const float*)d_in[21];
    const float* ppp_gam = (const float*)d_in[22];
    const float* ppp_bet = (const float*)d_in[23];
    const float* ppp_ow  = (const float*)d_in[24];
    const float* ppp_ob  = (const float*)d_in[25];
    float* out = (float*)d_out;

    k_down<<<(NB*C*HD*HD + 255)/256, 256>>>(x, down_w);
    k_conv_theta<<<NB*64, 256>>>(theta_w, theta_b);
    k_conv_pool_gphi<<<NB*64, 256>>>(g_w, g_b, phi_w, phi_b);
    k_pool_all<<<3*NB*64, 64>>>();
    k_levelconv_all<<<(3*NB*85*16 + 255)/256, 256>>>(ppg_pw, ppg_gam, ppg_bet,
                                                     ppt_pw, ppt_gam, ppt_bet,
                                                     ppp_pw, ppp_gam, ppp_bet);
    k_ppfinal<<<NB*(1024/64), 256>>>(0, ppg_ow, ppg_ob, 32);
    k_ppfinal<<<NB*(4096/64), 256>>>(1, ppt_ow, ppt_ob, 64);
    k_ppfinal<<<NB*(1024/64), 256>>>(2, ppp_ow, ppp_ob, 32);
    k_depth<<<(NB*4096 + NB*1024 + 255)/256, 256>>>(depth);
    k_attn_hmma<<<NB*32, 256>>>();
    k_zconv<<<NB*64, 256>>>(z_w, z_b);
    k_epi<<<(NB*C*H0*H0/4 + 255)/256, 256>>>(x, out);
}

// round 6
// speedup vs baseline: 2.4412x; 1.1068x over previous
#include <cuda_runtime.h>
#include <cuda_bf16.h>
#include <cuda_fp16.h>
#include <math.h>
#include <cstdint>

#define NB 4
#define C 128
#define CC 64
#define H0 256
#define HD 64
#define EPS6 1e-6f
#define BN_INV 0.9999950000374997f

// ---------- helpers ----------
__device__ __forceinline__ uint32_t s2u(const void* p){
    uint32_t a; asm("{ .reg .u64 t; cvta.to.shared.u64 t, %1; cvt.u32.u64 %0, t; }" : "=r"(a) : "l"(p)); return a;
}
__device__ __forceinline__ void ldsm4(uint32_t* r, uint32_t a){
    asm volatile("ldmatrix.sync.aligned.m8n8.x4.shared.b16 {%0,%1,%2,%3}, [%4];"
        : "=r"(r[0]),"=r"(r[1]),"=r"(r[2]),"=r"(r[3]) : "r"(a));
}
__device__ __forceinline__ void ldsm4t(uint32_t* r, uint32_t a){
    asm volatile("ldmatrix.sync.aligned.m8n8.x4.trans.shared.b16 {%0,%1,%2,%3}, [%4];"
        : "=r"(r[0]),"=r"(r[1]),"=r"(r[2]),"=r"(r[3]) : "r"(a));
}
__device__ __forceinline__ void mma16816(float* d, const uint32_t* a, uint32_t b0, uint32_t b1){
    asm volatile("mma.sync.aligned.m16n8k16.row.col.f32.bf16.bf16.f32 "
        "{%0,%1,%2,%3}, {%4,%5,%6,%7}, {%8,%9}, {%0,%1,%2,%3};"
        : "+f"(d[0]),"+f"(d[1]),"+f"(d[2]),"+f"(d[3])
        : "r"(a[0]),"r"(a[1]),"r"(a[2]),"r"(a[3]), "r"(b0),"r"(b1));
}
// exp(x) for x in [-1, 1]: half-and-square, Taylor deg 6, rel err < 6e-6. Pure FMA.
__device__ __forceinline__ float expp(float x){
    float h = 0.5f*x;
    float p = __fmaf_rn(h, 0.0013888889f, 0.0083333333f);
    p = __fmaf_rn(h, p, 0.0416666667f);
    p = __fmaf_rn(h, p, 0.1666666667f);
    p = __fmaf_rn(h, p, 0.5f);
    p = __fmaf_rn(h, p, 1.0f);
    p = __fmaf_rn(h, p, 1.0f);
    return p*p;
}

// ---------- scratch ----------
__device__ float g_xdown[NB*C*HD*HD];
__device__ float g_thin [NB*CC*HD*HD];
__device__ float g_g0   [NB*CC*1024];
__device__ float g_phi0 [NB*CC*1024];
__device__ float g_pool [3][NB*CC*85];
__device__ float g_ppc  [3][NB*85*16];
__device__ __align__(16) __nv_bfloat16 g_th_h [NB*4096*64];
__device__ __align__(16) __nv_bfloat16 g_phi_h[NB*1024*64];
__device__ __align__(16) __nv_bfloat16 g_gv_h [NB*1024*64];
__device__ uint32_t g_lg[NB*4096*512];      // fp16 logits, fragment-native layout
__device__ float g_yatt[NB*4096*CC];
__device__ float g_z[NB*C*4096];

// ---------- K1: depthwise stride-4 4x4 conv ----------
__global__ void k_down(const float* __restrict__ x, const float* __restrict__ dw){
    int idx = blockIdx.x*blockDim.x + threadIdx.x;
    if (idx >= NB*C*HD*HD) return;
    int j = idx & 63, i = (idx>>6) & 63, nc = idx>>12;
    int ch = nc & (C-1);
    const float* xb = x + ((size_t)nc<<16) + i*4*256 + j*4;
    const float* w = dw + ch*16;
    float s = 0.f;
    #pragma unroll
    for (int a=0; a<4; a++){
        float4 v = *(const float4*)(xb + a*256);
        s += v.x*w[a*4+0] + v.y*w[a*4+1] + v.z*w[a*4+2] + v.w*w[a*4+3];
    }
    g_xdown[idx] = s;
}

// ---------- K2: merged theta/g/phi 1x1 convs (+2x2 maxpool for g,phi) ----------
__global__ void k_convs(const float* __restrict__ tw, const float* __restrict__ tbias,
                        const float* __restrict__ gw, const float* __restrict__ gb,
                        const float* __restrict__ pw, const float* __restrict__ pb){
    __shared__ float xs[128][65];
    int bid = blockIdx.x;                  // NB*64 (8x8 tiles of 8x8 px)
    int n = bid >> 6; int tbk = bid & 63; int by = tbk>>3, bx = tbk&7;
    const float* xin = g_xdown + (size_t)n*C*4096;
    int base = by*8*64 + bx*8;
    for (int idx = threadIdx.x; idx < 128*64; idx += 256){
        int c_ = idx>>6, p = idx&63;
        xs[c_][p] = xin[c_*4096 + base + (p>>3)*64 + (p&7)];
    }
    __syncthreads();
    int o = threadIdx.x >> 2, py = threadIdx.x & 3;
    float ta[16], ga[16], pa[16];
    float tbi = tbias[o], gbi = gb[o], pbi = pb[o];
    #pragma unroll
    for (int i=0;i<16;i++){ ta[i]=tbi; ga[i]=gbi; pa[i]=pbi; }
    const float* two = tw + o*128;
    const float* gwo = gw + o*128;
    const float* pwo = pw + o*128;
    for (int c=0;c<128;c++){
        float wt = __ldg(&two[c]), wg = __ldg(&gwo[c]), wp = __ldg(&pwo[c]);
        #pragma unroll
        for (int i=0;i<16;i++){
            float xv = xs[c][py*16+i];
            ta[i]+=wt*xv; ga[i]+=wg*xv; pa[i]+=wp*xv;
        }
    }
    // theta out (full res)
    float* tout = g_thin + ((size_t)n*CC + o)*4096 + base;
    #pragma unroll
    for (int i=0;i<16;i++){
        int p = py*16 + i;
        tout[(p>>3)*64 + (p&7)] = ta[i];
    }
    // pooled g/phi
    int vy = by*4 + py;
    float* gout = g_g0  + ((size_t)n*CC+o)*1024 + vy*32 + bx*4;
    float* pout = g_phi0+ ((size_t)n*CC+o)*1024 + vy*32 + bx*4;
    #pragma unroll
    for (int px=0;px<4;px++){
        gout[px] = fmaxf(fmaxf(ga[2*px],ga[2*px+1]), fmaxf(ga[8+2*px],ga[8+2*px+1]));
        pout[px] = fmaxf(fmaxf(pa[2*px],pa[2*px+1]), fmaxf(pa[8+2*px],pa[8+2*px+1]));
    }
}

// ---------- K4: pyramid pools (all 3 branches) ----------
__global__ void k_pool_all(){
    __shared__ float s8[64], s4[16], s2[4];
    int bid = blockIdx.x;                 // 3*NB*64
    int br = bid >> 8; int nc = bid & 255;
    int H = (br==1) ? 64 : 32;
    const float* in = (br==0) ? g_g0 : (br==1) ? g_thin : g_phi0;
    const float* p = in + (size_t)nc*H*H;
    int t = threadIdx.x;
    int k0 = H >> 3;
    int cy = t>>3, cx = t&7;
    const float* cell = p + (cy*k0)*H + cx*k0;
    float s = 0.f;
    if (k0 == 8){
        #pragma unroll
        for (int a=0;a<8;a++){
            float4 v1 = *(const float4*)(cell + a*64);
            float4 v2 = *(const float4*)(cell + a*64 + 4);
            s += v1.x+v1.y+v1.z+v1.w + v2.x+v2.y+v2.z+v2.w;
        }
    } else {
        #pragma unroll
        for (int a=0;a<4;a++){
            float4 v = *(const float4*)(cell + a*32);
            s += v.x+v.y+v.z+v.w;
        }
    }
    s8[t] = s;
    __syncthreads();
    float* ob = g_pool[br] + nc*85;
    ob[t] = s8[t] / (float)(k0*k0);
    if (t < 16){
        int yy=t>>2, xx=t&3;
        float v = s8[(2*yy)*8+2*xx] + s8[(2*yy)*8+2*xx+1] + s8[(2*yy+1)*8+2*xx] + s8[(2*yy+1)*8+2*xx+1];
        s4[t]=v; ob[64+t] = v / (float)(4*k0*k0);
    }
    __syncthreads();
    if (t < 4){
        int yy=t>>1, xx=t&1;
        float v = s4[(2*yy)*4+2*xx] + s4[(2*yy)*4+2*xx+1] + s4[(2*yy+1)*4+2*xx] + s4[(2*yy+1)*4+2*xx+1];
        s2[t]=v; ob[80+t] = v / (float)(16*k0*k0);
    }
    __syncthreads();
    if (t == 0) ob[84] = (s2[0]+s2[1]+s2[2]+s2[3]) / (float)(64*k0*k0);
}

// ---------- K5: level convs (all 3 branches) ----------
__global__ void k_levelconv_all(const float* __restrict__ pw0, const float* __restrict__ g0, const float* __restrict__ b0,
                                const float* __restrict__ pw1, const float* __restrict__ g1, const float* __restrict__ b1,
                                const float* __restrict__ pw2, const float* __restrict__ g2, const float* __restrict__ b2){
    int idx = blockIdx.x*blockDim.x + threadIdx.x;
    if (idx >= 3*NB*85*16) return;
    int br = idx / (NB*85*16);
    int rem = idx % (NB*85*16);
    int o = rem & 15, s = (rem>>4) % 85, n = rem / (85*16);
    const float* pw = (br==0)?pw0:(br==1)?pw1:pw2;
    const float* gamma = (br==0)?g0:(br==1)?g1:g2;
    const float* beta = (br==0)?b0:(br==1)?b1:b2;
    int lvl = (s<64) ? 0 : (s<80 ? 1 : (s<84 ? 2 : 3));
    const float* w = pw + (lvl*16+o)*64;
    const float* pl = g_pool[br] + n*64*85 + s;
    float acc = 0.f;
    for (int c=0;c<64;c++) acc += w[c]*pl[c*85];
    acc = acc*BN_INV*gamma[lvl*16+o] + beta[lvl*16+o];
    g_ppc[br][(n*85+s)*16+o] = fmaxf(acc, 0.f);
}

// ---------- K6: pyramid final conv -> bf16 ----------
__global__ void k_ppfinal(int br, const float* __restrict__ ow, const float* __restrict__ ob, int H){
    __shared__ float xs[64][65];
    __shared__ float us[64][65];
    int P = H*H;
    int bpn = P >> 6;
    int bid = blockIdx.x;
    int n = bid / bpn; int t0 = (bid % bpn) << 6;
    const float* X = (br==0) ? g_g0 : (br==1) ? g_thin : g_phi0;
    const float* xin = X + (size_t)n*CC*P;
    for (int idx = threadIdx.x; idx < 64*64; idx += 256){
        int c_ = idx>>6, p = idx&63;
        xs[c_][p] = xin[c_*P + t0 + p];
    }
    const float* pn = g_ppc[br] + n*85*16;
    float invH = 1.0f / (float)H;
    for (int e = threadIdx.x; e < 4096; e += 256){
        int p = e>>6, u = e&63;
        int lvl = u>>4, j = u&15;
        int pix = t0 + p; int y = pix / H, x = pix % H;
        int ps = 8 >> lvl;
        int off = (lvl==0) ? 0 : (lvl==1 ? 64 : (lvl==2 ? 80 : 84));
        float sy = fminf(fmaxf((y+0.5f)*ps*invH - 0.5f, 0.f), (float)(ps-1));
        float sx = fminf(fmaxf((x+0.5f)*ps*invH - 0.5f, 0.f), (float)(ps-1));
        int yl=(int)sy; int yh=min(yl+1, ps-1); float fy=sy-yl;
        int xl=(int)sx; int xh=min(xl+1, ps-1); float fx=sx-xl;
        const float* b00 = pn + (off + yl*ps + xl)*16;
        const float* b01 = pn + (off + yl*ps + xh)*16;
        const float* b10 = pn + (off + yh*ps + xl)*16;
        const float* b11 = pn + (off + yh*ps + xh)*16;
        us[p][u] = (b00[j]*(1.f-fx)+b01[j]*fx)*(1.f-fy) + (b10[j]*(1.f-fx)+b11[j]*fx)*fy;
    }
    __syncthreads();
    int o = threadIdx.x >> 2, grp = threadIdx.x & 3;
    const float* wo = ow + o*128;
    float acc[16]; float bo = ob[o];
    #pragma unroll
    for (int i=0;i<16;i++) acc[i]=bo;
    for (int c=0;c<64;c++){
        float wv = __ldg(&wo[c]);
        #pragma unroll
        for (int i=0;i<16;i++) acc[i] += wv*xs[c][grp*16+i];
    }
    for (int u=0;u<64;u++){
        float wv = __ldg(&wo[64+u]);
        #pragma unroll
        for (int i=0;i<16;i++) acc[i] += wv*us[grp*16+i][u];
    }
    #pragma unroll
    for (int i=0;i<16;i++){
        int pix = t0 + grp*16 + i;
        float v = acc[i];
        if (br == 1)      g_th_h [((size_t)n*4096 + pix)*64 + o] = __float2bfloat16(v);
        else if (br == 0) g_gv_h [((size_t)n*1024 + pix)*64 + o] = __float2bfloat16(v);
        else              g_phi_h[((size_t)n*1024 + pix)*64 + o] = __float2bfloat16(v);
    }
}

// ---------- bilinear on 256x256 ----------
__device__ __forceinline__ float bil256(const float* p, float sy, float sx){
    int yl=(int)sy; int yh=min(yl+1,255); float fy=sy-yl;
    int xl=(int)sx; int xh=min(xl+1,255); float fx=sx-xl;
    return (p[yl*256+xl]*(1.f-fx)+p[yl*256+xh]*fx)*(1.f-fy)
         + (p[yh*256+xl]*(1.f-fx)+p[yh*256+xh]*fx)*fy;
}

// ---------- K8: HMMA attention, logits stored fp16 (L2-resident). grid=NB*32=128, 256 thr ----------
__global__ void __launch_bounds__(256,1) k_attn_hmma(const float* __restrict__ depth){
    __shared__ __align__(16) __nv_bfloat16 sA[128*72];
    __shared__ __align__(16) __nv_bfloat16 sB[128*72];
    __shared__ float2 d2s[1024];
    __shared__ float d1s[128];
    int tid = threadIdx.x, w = tid>>5, lane = tid&31;
    int n = blockIdx.x>>5, q0 = (blockIdx.x&31)*128;

    // depth resizes computed in-kernel
    const float* dm = depth + (size_t)n*65536;
    for (int i=tid;i<1024;i+=256){
        int yy=i>>5, xx=i&31;
        float d2 = bil256(dm, (float)(yy*255)/31.f, (float)(xx*255)/31.f);
        d2s[i] = make_float2(d2, __fdividef(1.f, d2+EPS6));
    }
    if (tid < 128){
        int q = q0 + tid; int yy=q>>6, xx=q&63;
        d1s[tid] = bil256(dm, (float)(yy*255)/63.f, (float)(xx*255)/63.f);
    }
    const uint4* qg = (const uint4*)(g_th_h + ((size_t)(n*4096+q0))*64);
    for (int i=tid;i<1024;i+=256)
        *(uint4*)&sA[(i>>3)*72 + (i&7)*8] = qg[i];
    __syncthreads();
    uint32_t sAu = s2u(sA), sBu = s2u(sB);
    uint32_t aQ[4][4];
    {
        int arow = w*16 + (lane&15);
        int acol = (lane>>4)<<3;
        #pragma unroll
        for (int kb=0;kb<4;kb++)
            ldsm4(aQ[kb], sAu + (uint32_t)((arow*72 + kb*16 + acol)*2));
    }
    int ra = lane>>2, colb = (lane&3)*2;
    float d1a = d1s[w*16+ra], d1b = d1s[w*16+ra+8];
    float ir1a = __fdividef(1.f,d1a+EPS6), ir1b = __fdividef(1.f,d1b+EPS6);
    __syncthreads();

    int brow = (lane&7) + ((lane&16)?8:0);
    int bcol = (lane&8)?8:0;
    int grow = (lane&7) + ((lane&8)?8:0);
    int gcol = (lane&16)?8:0;
    const uint4* phg = (const uint4*)(g_phi_h + (size_t)n*65536);
    const uint4* gg  = (const uint4*)(g_gv_h + (size_t)n*65536);
    uint32_t* lg = g_lg + ((size_t)(n*4096 + q0))*512;
    int lrowa = (w*16+ra)*512, lrowb = (w*16+ra+8)*512;

    float m1a=-1e30f,s1a=0.f,m2a=-1e30f,s2a=0.f;
    float m1b=-1e30f,s1b=0.f,m2b=-1e30f,s2b=0.f;

    // preload phi tile 0 -> sA
    for (int i=tid;i<1024;i+=256)
        *(uint4*)&sA[(i>>3)*72+(i&7)*8] = phg[i];
    __syncthreads();

    // ===== pass 1: logits via MMA -> store fp16; online stats =====
    for (int t=0;t<8;t++){
        const __nv_bfloat16* cur = (t&1) ? sB : sA;
        __nv_bfloat16* nxt = (t&1) ? sA : sB;
        uint32_t curu = (t&1) ? sBu : sAu;
        uint4 pre[4];
        if (t<7){
            #pragma unroll
            for (int k=0;k<4;k++) pre[k] = phg[(t+1)*1024 + tid + k*256];
        }
        float L[16][4];
        #pragma unroll
        for (int nt=0;nt<16;nt++){ L[nt][0]=0.f;L[nt][1]=0.f;L[nt][2]=0.f;L[nt][3]=0.f; }
        #pragma unroll
        for (int kb=0;kb<4;kb++){
            #pragma unroll
            for (int ng=0;ng<8;ng++){
                uint32_t bq[4];
                ldsm4(bq, curu + (uint32_t)(((ng*16+brow)*72 + kb*16 + bcol)*2));
                mma16816(L[2*ng], aQ[kb], bq[0], bq[1]);
                mma16816(L[2*ng+1], aQ[kb], bq[2], bq[3]);
            }
        }
        if (t<7){
            #pragma unroll
            for (int k=0;k<4;k++){
                int i = tid + k*256;
                *(uint4*)&nxt[(i>>3)*72+(i&7)*8] = pre[k];
            }
        }
        // store logits fp16 + stats
        int cw = t*64 + (lane&3);
        float lma=-1e30f,lmb=-1e30f;
        #pragma unroll
        for (int nt=0;nt<16;nt++){
            __half2 ha = __floats2half2_rn(L[nt][0], L[nt][1]);
            __half2 hb = __floats2half2_rn(L[nt][2], L[nt][3]);
            lg[lrowa + cw + nt*4] = *(uint32_t*)&ha;
            lg[lrowb + cw + nt*4] = *(uint32_t*)&hb;
            float2 dp = d2s[t*128+nt*8+colb];
            float2 dq = d2s[t*128+nt*8+colb+1];
            float r0 = fminf(d1a*dp.y, dp.x*ir1a);
            float r1 = fminf(d1a*dq.y, dq.x*ir1a);
            float r2 = fminf(d1b*dp.y, dp.x*ir1b);
            float r3 = fminf(d1b*dq.y, dq.x*ir1b);
            m2a = fmaxf(m2a, fmaxf(r0,r1));
            m2b = fmaxf(m2b, fmaxf(r2,r3));
            s2a += expp(r0-1.f) + expp(r1-1.f);
            s2b += expp(r2-1.f) + expp(r3-1.f);
            lma = fmaxf(lma, fmaxf(L[nt][0],L[nt][1]));
            lmb = fmaxf(lmb, fmaxf(L[nt][2],L[nt][3]));
        }
        float mn;
        mn = fmaxf(m1a,lma); s1a *= __expf(m1a-mn); m1a = mn;
        mn = fmaxf(m1b,lmb); s1b *= __expf(m1b-mn); m1b = mn;
        #pragma unroll
        for (int nt=0;nt<16;nt++){
            s1a += __expf(L[nt][0]-m1a) + __expf(L[nt][1]-m1a);
            s1b += __expf(L[nt][2]-m1b) + __expf(L[nt][3]-m1b);
        }
        __syncthreads();
    }

    // quad reductions
    #pragma unroll
    for (int o=1;o<=2;o<<=1){
        float mo, so, mn;
        mo=__shfl_xor_sync(~0u,m1a,o); so=__shfl_xor_sync(~0u,s1a,o);
        mn=fmaxf(m1a,mo); s1a=s1a*__expf(m1a-mn)+so*__expf(mo-mn); m1a=mn;
        mo=__shfl_xor_sync(~0u,m1b,o); so=__shfl_xor_sync(~0u,s1b,o);
        mn=fmaxf(m1b,mo); s1b=s1b*__expf(m1b-mn)+so*__expf(mo-mn); m1b=mn;
        s2a += __shfl_xor_sync(~0u,s2a,o);
        s2b += __shfl_xor_sync(~0u,s2b,o);
        m2a = fmaxf(m2a,__shfl_xor_sync(~0u,m2a,o));
        m2b = fmaxf(m2b,__shfl_xor_sync(~0u,m2b,o));
    }
    float S2a = s2a * expp(1.f - m2a);
    float S2b = s2b * expp(1.f - m2b);
    float c1a=__fdividef(1.f,s1a*S2a), mm12a=m1a+m2a;
    float c1b=__fdividef(1.f,s1b*S2b), mm12b=m1b+m2b;

    // ===== pass 2: load logits, E, Y mma =====
    float Y[8][4];
    #pragma unroll
    for (int i=0;i<8;i++){ Y[i][0]=0.f;Y[i][1]=0.f;Y[i][2]=0.f;Y[i][3]=0.f; }
    float s3a=0.f, s3b=0.f;
    // preload g tile 0 -> sA
    for (int i=tid;i<1024;i+=256)
        *(uint4*)&sA[(i>>3)*72+(i&7)*8] = gg[i];
    __syncthreads();
    for (int t=0;t<8;t++){
        uint32_t curu = (t&1) ? sBu : sAu;
        __nv_bfloat16* nxt = (t&1) ? sA : sB;
        uint4 pre[4];
        if (t<7){
            #pragma unroll
            for (int k=0;k<4;k++) pre[k] = gg[(t+1)*1024 + tid + k*256];
        }
        int cw = t*64 + (lane&3);
        uint32_t lwa[16], lwb[16];
        #pragma unroll
        for (int nt=0;nt<16;nt++){
            lwa[nt] = lg[lrowa + cw + nt*4];
            lwb[nt] = lg[lrowb + cw + nt*4];
        }
        uint32_t ek[8][4];
        #pragma unroll
        for (int nt=0;nt<16;nt++){
            float2 la = __half22float2(*(__half2*)&lwa[nt]);
            float2 lb = __half22float2(*(__half2*)&lwb[nt]);
            float2 dp = d2s[t*128+nt*8+colb];
            float2 dq = d2s[t*128+nt*8+colb+1];
            float r0 = fminf(d1a*dp.y, dp.x*ir1a);
            float r1 = fminf(d1a*dq.y, dq.x*ir1a);
            float r2 = fminf(d1b*dp.y, dp.x*ir1b);
            float r3 = fminf(d1b*dq.y, dq.x*ir1b);
            float e0 = expp(c1a*__expf(la.x+r0-mm12a));
            float e1 = expp(c1a*__expf(la.y+r1-mm12a));
            float e2 = expp(c1b*__expf(lb.x+r2-mm12b));
            float e3 = expp(c1b*__expf(lb.y+r3-mm12b));
            s3a += e0+e1; s3b += e2+e3;
            __nv_bfloat162 pa2 = __floats2bfloat162_rn(e0,e1);
            __nv_bfloat162 pb2 = __floats2bfloat162_rn(e2,e3);
            int kb = nt>>1, hh = (nt&1)<<1;
            ek[kb][hh]   = *(uint32_t*)&pa2;
            ek[kb][hh+1] = *(uint32_t*)&pb2;
        }
        #pragma unroll
        for (int kb=0;kb<8;kb++){
            #pragma unroll
            for (int np=0;np<4;np++){
                uint32_t bg[4];
                ldsm4t(bg, curu + (uint32_t)(((kb*16+grow)*72 + np*16 + gcol)*2));
                mma16816(Y[2*np], ek[kb], bg[0], bg[1]);
                mma16816(Y[2*np+1], ek[kb], bg[2], bg[3]);
            }
        }
        if (t<7){
            #pragma unroll
            for (int k=0;k<4;k++){
                int i = tid + k*256;
                *(uint4*)&nxt[(i>>3)*72+(i&7)*8] = pre[k];
            }
        }
        __syncthreads();
    }
    s3a += __shfl_xor_sync(~0u,s3a,1); s3a += __shfl_xor_sync(~0u,s3a,2);
    s3b += __shfl_xor_sync(~0u,s3b,1); s3b += __shfl_xor_sync(~0u,s3b,2);
    float i3a = __fdividef(1.f,s3a), i3b = __fdividef(1.f,s3b);
    int qa = q0 + w*16 + ra;
    float* ya = g_yatt + ((size_t)(n*4096+qa))*64;
    float* yb = ya + 8*64;
    #pragma unroll
    for (int np2=0;np2<8;np2++){
        *(float2*)&ya[np2*8+colb] = make_float2(Y[np2][0]*i3a, Y[np2][1]*i3a);
        *(float2*)&yb[np2*8+colb] = make_float2(Y[np2][2]*i3b, Y[np2][3]*i3b);
    }
}

// ---------- K9: z conv ----------
__global__ void k_zconv(const float* __restrict__ zw, const float* __restrict__ zb){
    __shared__ float ys[64][68];
    int bid = blockIdx.x;
    int n = bid >> 6; int t0 = (bid & 63) << 6;
    const float* yb = g_yatt + ((size_t)n*4096 + t0)*64;
    for (int idx = threadIdx.x; idx < 4096; idx += 256)
        ys[idx>>6][idx&63] = yb[idx];
    __syncthreads();
    int o = threadIdx.x >> 1, grp = threadIdx.x & 1;
    float4 wreg[16];
    const float4* wo4 = (const float4*)(zw + o*64);
    #pragma unroll
    for (int i=0;i<16;i++) wreg[i] = __ldg(&wo4[i]);
    float bo = zb[o];
    float* zp = g_z + ((size_t)n*C + o)*4096 + t0 + grp*32;
    #pragma unroll 4
    for (int p=0;p<32;p++){
        const float4* yr = (const float4*)&ys[grp*32+p][0];
        float acc = bo;
        #pragma unroll
        for (int i=0;i<16;i++){
            float4 v = yr[i];
            acc += wreg[i].x*v.x + wreg[i].y*v.y + wreg[i].z*v.z + wreg[i].w*v.w;
        }
        zp[p] = acc;
    }
}

// ---------- K10: epilogue ----------
__global__ void k_epi(const float* __restrict__ x, float* __restrict__ out){
    int idx = blockIdx.x*blockDim.x + threadIdx.x;
    if (idx >= NB*C*H0*H0/4) return;
    int xb4 = (idx & 63) << 2;
    int Y = (idx>>6) & 255;
    int nch = idx >> 14;
    float sy = (float)(Y*63)/255.f;
    int yl=(int)sy; int yh=min(yl+1,63); float fy=sy-yl;
    const float* z0 = g_z + (size_t)nch*4096 + yl*64;
    const float* z1 = g_z + (size_t)nch*4096 + yh*64;
    float4 r;
    float* rp = &r.x;
    #pragma unroll
    for (int k=0;k<4;k++){
        int X_ = xb4 + k;
        float sx = (float)(X_*63)/255.f;
        int xl=(int)sx; int xh=min(xl+1,63); float fx=sx-xl;
        rp[k] = (z0[xl]*(1.f-fx)+z0[xh]*fx)*(1.f-fy)
              + (z1[xl]*(1.f-fx)+z1[xh]*fx)*fy;
    }
    float4 xin = *(const float4*)(x + ((size_t)idx<<2));
    r.x += xin.x; r.y += xin.y; r.z += xin.z; r.w += xin.w;
    *(float4*)(out + ((size_t)idx<<2)) = r;
}

// ---------- host ----------
extern "C" void kernel_launch(void* const* d_in, const int* in_sizes, int n_in,
                              void* d_out, int out_size){
    const float* x       = (const float*)d_in[0];
    const float* depth   = (const float*)d_in[1];
    const float* down_w  = (const float*)d_in[2];
    const float* theta_w = (const float*)d_in[3];
    const float* theta_b = (const float*)d_in[4];
    const float* phi_w   = (const float*)d_in[5];
    const float* phi_b   = (const float*)d_in[6];
    const float* g_w     = (const float*)d_in[7];
    const float* g_b     = (const float*)d_in[8];
    const float* z_w     = (const float*)d_in[9];
    const float* z_b     = (const float*)d_in[10];
    const float* ppg_pw  = (const float*)d_in[11];
    const float* ppg_gam = (const float*)d_in[12];
    const float* ppg_bet = (const float*)d_in[13];
    const float* ppg_ow  = (const float*)d_in[14];
    const float* ppg_ob  = (const float*)d_in[15];
    const float* ppt_pw  = (const float*)d_in[16];
    const float* ppt_gam = (const float*)d_in[17];
    const float* ppt_bet = (const float*)d_in[18];
    const float* ppt_ow  = (const float*)d_in[19];
    const float* ppt_ob  = (const float*)d_in[20];
    const float* ppp_pw  = (const float*)d_in[21];
    const float* ppp_gam = (const float*)d_in[22];
    const float* ppp_bet = (const float*)d_in[23];
    const float* ppp_ow  = (const float*)d_in[24];
    const float* ppp_ob  = (const float*)d_in[25];
    float* out = (float*)d_out;

    k_down<<<(NB*C*HD*HD + 255)/256, 256>>>(x, down_w);
    k_convs<<<NB*64, 256>>>(theta_w, theta_b, g_w, g_b, phi_w, phi_b);
    k_pool_all<<<3*NB*64, 64>>>();
    k_levelconv_all<<<(3*NB*85*16 + 255)/256, 256>>>(ppg_pw, ppg_gam, ppg_bet,
                                                     ppt_pw, ppt_gam, ppt_bet,
                                                     ppp_pw, ppp_gam, ppp_bet);
    k_ppfinal<<<NB*(1024/64), 256>>>(0, ppg_ow, ppg_ob, 32);
    k_ppfinal<<<NB*(4096/64), 256>>>(1, ppt_ow, ppt_ob, 64);
    k_ppfinal<<<NB*(1024/64), 256>>>(2, ppp_ow, ppp_ob, 32);
    k_attn_hmma<<<NB*32, 256>>>(depth);
    k_zconv<<<NB*64, 256>>>(z_w, z_b);
    k_epi<<<(NB*C*H0*H0/4 + 255)/256, 256>>>(x, out);
}